// round 12
// baseline (speedup 1.0000x reference)
#include <cuda_runtime.h>
#include <cuda_fp16.h>
#include <cstdint>

// ---------------------------------------------------------------------------
// Problem constants
// ---------------------------------------------------------------------------
#define Bv     4
#define Nseq   8192
#define EMBED  1024
#define HEADS  16
#define HDIM   64
#define RANK   512
#define MTOK   (Bv * Nseq)          // 32768
#define BH     (Bv * HEADS)         // 64

// ---------------------------------------------------------------------------
// Scratch (__device__ globals; allocation forbidden)
// ---------------------------------------------------------------------------
__device__ __half g_inH3[(size_t)3 * MTOK * EMBED];
__device__ __half g_yH3 [(size_t)3 * MTOK * RANK];
__device__ __half g_QH [MTOK * EMBED];
__device__ __half g_KH [MTOK * EMBED];
__device__ __half g_VH [MTOK * EMBED];
__device__ __half g_atH[MTOK * EMBED];

#define W_QD 0
#define W_QU (W_QD + RANK*EMBED)
#define W_KD (W_QU + EMBED*RANK)
#define W_KU (W_KD + RANK*EMBED)
#define W_VD (W_KU + EMBED*RANK)
#define W_VU (W_VD + RANK*EMBED)
#define W_O  (W_VU + EMBED*RANK)
#define W_TOT (W_O + EMBED*EMBED)
__device__ __half g_wH[W_TOT];

#define KV_ELEMS (BH * HDIM * HDIM)
#define KS_ELEMS (BH * HDIM)
__device__ float  g_kvks[KV_ELEMS + KS_ELEMS];
__device__ __half g_kvTh[KV_ELEMS];
__device__ float  g_dinv[BH * Nseq];

// ---------------------------------------------------------------------------
// helpers
// ---------------------------------------------------------------------------
__device__ __forceinline__ uint32_t smem_u32(const void* p) {
    uint32_t a;
    asm("{ .reg .u64 t; cvta.to.shared.u64 t, %1; cvt.u32.u64 %0, t; }"
        : "=r"(a) : "l"(p));
    return a;
}

__device__ __forceinline__ void ldsm4(uint32_t* r, uint32_t addr) {
    asm volatile("ldmatrix.sync.aligned.m8n8.x4.shared.b16 {%0,%1,%2,%3}, [%4];"
        : "=r"(r[0]), "=r"(r[1]), "=r"(r[2]), "=r"(r[3]) : "r"(addr));
}

__device__ __forceinline__ void ldsm4t(uint32_t* r, uint32_t addr) {
    asm volatile("ldmatrix.sync.aligned.m8n8.x4.trans.shared.b16 {%0,%1,%2,%3}, [%4];"
        : "=r"(r[0]), "=r"(r[1]), "=r"(r[2]), "=r"(r[3]) : "r"(addr));
}

__device__ __forceinline__ void mma16816(float* c, const uint32_t* a, const uint32_t* b) {
    asm volatile("mma.sync.aligned.m16n8k16.row.col.f32.f16.f16.f32 "
        "{%0,%1,%2,%3}, {%4,%5,%6,%7}, {%8,%9}, {%0,%1,%2,%3};"
        : "+f"(c[0]), "+f"(c[1]), "+f"(c[2]), "+f"(c[3])
        : "r"(a[0]), "r"(a[1]), "r"(a[2]), "r"(a[3]), "r"(b[0]), "r"(b[1]));
}

#define CP_ASYNC16(so, ga) \
    asm volatile("cp.async.cg.shared.global [%0], [%1], 16;\n" :: "r"(so), "l"(ga))
#define CP_COMMIT() asm volatile("cp.async.commit_group;\n" ::: "memory")
#define CP_WAIT(n)  asm volatile("cp.async.wait_group %0;\n" :: "n"(n) : "memory")

// ---------------------------------------------------------------------------
// cvt3: q/k/v fp32 -> fp16, one launch, z selects tensor. 8 elems/thread.
// ---------------------------------------------------------------------------
__global__ void cvt3_kernel(const float* __restrict__ x0,
                            const float* __restrict__ x1,
                            const float* __restrict__ x2)
{
    const int z = blockIdx.y;
    const float* x = (z == 0) ? x0 : (z == 1) ? x1 : x2;
    __half* dst = g_inH3 + (size_t)z * (MTOK * EMBED);
    const int i = blockIdx.x * 256 + threadIdx.x;
    const float4* xp = reinterpret_cast<const float4*>(x) + 2 * (size_t)i;
    float4 a = xp[0], b = xp[1];
    __half2* yp = reinterpret_cast<__half2*>(dst) + 4 * (size_t)i;
    yp[0] = __floats2half2_rn(a.x, a.y);
    yp[1] = __floats2half2_rn(a.z, a.w);
    yp[2] = __floats2half2_rn(b.x, b.y);
    yp[3] = __floats2half2_rn(b.z, b.w);
}

// ---------------------------------------------------------------------------
// wcvt: all 7 weights fp32 -> fp16 in one launch
// ---------------------------------------------------------------------------
#define WSEG4 (RANK * EMBED / 4)
__global__ void wcvt_kernel(const float* __restrict__ p0, const float* __restrict__ p1,
                            const float* __restrict__ p2, const float* __restrict__ p3,
                            const float* __restrict__ p4, const float* __restrict__ p5,
                            const float* __restrict__ p6)
{
    const int i = blockIdx.x * 256 + threadIdx.x;
    int seg, off;
    if (i >= 6 * WSEG4) { seg = 6; off = i - 6 * WSEG4; }
    else                { seg = i / WSEG4; off = i % WSEG4; }
    const float* ps[7] = {p0, p1, p2, p3, p4, p5, p6};
    float4 v = reinterpret_cast<const float4*>(ps[seg])[off];
    __half2* yp = reinterpret_cast<__half2*>(g_wH) + 2 * (size_t)i;
    yp[0] = __floats2half2_rn(v.x, v.y);
    yp[1] = __floats2half2_rn(v.z, v.w);
}

// ---------------------------------------------------------------------------
// fused mma.sync fp16 NT GEMM. Tile 256x128, BK=64, 16 warps (4x4, 64x32 warp
// tile), 3-stage cp.async, 1 CTA/SM (RF-bound).
// KIND 0: down3. KIND 1: up3 (bias, elu for z<2). KIND 2: Wo (fp32 + bias)
// ---------------------------------------------------------------------------
#define BKC        64
#define RSTRIDE_B  144
#define A_TILE_BY  (256 * RSTRIDE_B)        // 36864
#define B_TILE_BY  (128 * RSTRIDE_B)        // 18432
#define STAGE_BY   (A_TILE_BY + B_TILE_BY)  // 55296
#define NSTAGE     3
#define SMEM_GEMM  (NSTAGE * STAGE_BY)      // 165888
#define OFF_A      0
#define OFF_B      A_TILE_BY

__device__ __forceinline__ void load_stage_mma(
    uint32_t sb, int tid, int s, int k0,
    const __half* __restrict__ A, const __half* __restrict__ B,
    int K, int aRow0, int bRow0)
{
    const uint32_t stage = sb + (uint32_t)s * STAGE_BY;
#pragma unroll
    for (int i = 0; i < 6; ++i) {
        int idx = tid + i * 512;            // 0..3071
        const __half* gp;
        int r0, row, cb;
        uint32_t tbase;
        if (idx < 2048) {                   // A: 256 rows x 8 chunks
            row = idx >> 3; cb = idx & 7;
            gp = A; r0 = aRow0; tbase = OFF_A;
        } else {                            // B: 128 rows x 8 chunks
            int w = idx - 2048;
            row = w >> 3; cb = w & 7;
            gp = B; r0 = bRow0; tbase = OFF_B;
        }
        const void* ga = gp + (size_t)(r0 + row) * K + k0 + cb * 8;
        uint32_t so = stage + tbase + (uint32_t)row * RSTRIDE_B + cb * 16;
        CP_ASYNC16(so, ga);
    }
    CP_COMMIT();
}

template <int KIND>
__global__ __launch_bounds__(512, 1) void gemm_fused(
    const float* __restrict__ b0, const float* __restrict__ b1,
    const float* __restrict__ b2, float* __restrict__ outF)
{
    constexpr int NN = (KIND == 0) ? RANK : EMBED;
    constexpr int KK = (KIND == 0) ? EMBED : ((KIND == 1) ? RANK : EMBED);

    extern __shared__ char smem[];
    const uint32_t sb = smem_u32(smem);
    const int tid = threadIdx.x;
    const int wid = tid >> 5;
    const int lane = tid & 31;
    const int bn = blockIdx.x, bm = blockIdx.y;
    const int z = (KIND == 2) ? 0 : blockIdx.z;
    const int warp_m = wid >> 2;            // 0..3 (64 rows each)
    const int warp_n = wid & 3;             // 0..3 (32 cols each)
    const int aRow0 = bm * 256, bRow0 = bn * 128;

    const __half* A;
    const __half* B;
    __half* Ch = nullptr;
    const float* bias = nullptr;
    bool elu = false;
    if (KIND == 0) {
        A = g_inH3 + (size_t)z * (MTOK * EMBED);
        B = g_wH + (size_t)z * (2 * RANK * EMBED);
        Ch = g_yH3 + (size_t)z * (MTOK * RANK);
    } else if (KIND == 1) {
        A = g_yH3 + (size_t)z * (MTOK * RANK);
        B = g_wH + W_QU + (size_t)z * (2 * RANK * EMBED);
        bias = (z == 0) ? b0 : (z == 1) ? b1 : b2;
        Ch = (z == 0) ? g_QH : (z == 1) ? g_KH : g_VH;
        elu = (z < 2);
    } else {
        A = g_atH;
        B = g_wH + W_O;
        bias = b0;
    }

    float acc[4][4][4];
#pragma unroll
    for (int mt = 0; mt < 4; ++mt)
#pragma unroll
        for (int nt = 0; nt < 4; ++nt)
#pragma unroll
            for (int j = 0; j < 4; ++j) acc[mt][nt][j] = 0.f;

    const int nch = KK / BKC;

    load_stage_mma(sb, tid, 0, 0,   A, B, KK, aRow0, bRow0);
    load_stage_mma(sb, tid, 1, BKC, A, B, KK, aRow0, bRow0);

    const int a_r = lane & 15;
    const int a_c = (lane >> 4) * 8;
    const int b_n = ((lane >> 4) << 3) + (lane & 7);
    const int b_k = ((lane >> 3) & 1) * 8;

    for (int c = 0; c < nch; ++c) {
        if (c == nch - 1) { CP_WAIT(0); } else { CP_WAIT(1); }
        __syncthreads();

        if (c + 2 < nch)
            load_stage_mma(sb, tid, (c + 2) % NSTAGE, (c + 2) * BKC,
                           A, B, KK, aRow0, bRow0);

        const uint32_t st = sb + (uint32_t)(c % NSTAGE) * STAGE_BY;
#pragma unroll
        for (int ks = 0; ks < 4; ++ks) {
            const int k0 = ks * 16;
            uint32_t ar[4][4];
#pragma unroll
            for (int mt = 0; mt < 4; ++mt) {
                uint32_t off = (uint32_t)(warp_m * 64 + mt * 16 + a_r) * RSTRIDE_B
                             + (uint32_t)(k0 + a_c) * 2;
                ldsm4(ar[mt], st + OFF_A + off);
            }
            uint32_t br[4][2];
#pragma unroll
            for (int nt2 = 0; nt2 < 2; ++nt2) {
                uint32_t off = (uint32_t)(warp_n * 32 + nt2 * 16 + b_n) * RSTRIDE_B
                             + (uint32_t)(k0 + b_k) * 2;
                uint32_t t4[4];
                ldsm4(t4, st + OFF_B + off);
                br[nt2*2][0] = t4[0]; br[nt2*2][1] = t4[1];
                br[nt2*2+1][0] = t4[2]; br[nt2*2+1][1] = t4[3];
            }
#pragma unroll
            for (int mt = 0; mt < 4; ++mt)
#pragma unroll
                for (int nt = 0; nt < 4; ++nt)
                    mma16816(acc[mt][nt], ar[mt], br[nt]);
        }
    }

    // epilogue
#pragma unroll
    for (int mt = 0; mt < 4; ++mt) {
#pragma unroll
        for (int nt = 0; nt < 4; ++nt) {
            const int row0 = bm * 256 + warp_m * 64 + mt * 16 + (lane >> 2);
            const int col  = bn * 128 + warp_n * 32 + nt * 8 + (lane & 3) * 2;
#pragma unroll
            for (int h = 0; h < 2; ++h) {
                const int row = row0 + h * 8;
                float f0 = acc[mt][nt][h * 2 + 0];
                float f1 = acc[mt][nt][h * 2 + 1];
                if (KIND >= 1) {
                    f0 += __ldg(bias + col);
                    f1 += __ldg(bias + col + 1);
                }
                if (KIND == 1 && elu) {
                    f0 = (f0 > 0.f) ? (f0 + 1.f) : __expf(f0);
                    f1 = (f1 > 0.f) ? (f1 + 1.f) : __expf(f1);
                }
                if (KIND == 2) {
                    *reinterpret_cast<float2*>(outF + (size_t)row * NN + col) =
                        make_float2(f0, f1);
                } else {
                    *reinterpret_cast<__half2*>(Ch + (size_t)row * NN + col) =
                        __floats2half2_rn(f0, f1);
                }
            }
        }
    }
}

// ---------------------------------------------------------------------------
// zero kernel
// ---------------------------------------------------------------------------
__global__ void zero_kernel(float* __restrict__ p, int n)
{
    int i = blockIdx.x * blockDim.x + threadIdx.x;
    if (i < n) p[i] = 0.f;
}

// ---------------------------------------------------------------------------
// kv via MMA: kv[bh][d][e] += sum_n k[n,d]*v[n,e]
// ---------------------------------------------------------------------------
#define KVNCH   4
#define KVTOK   (Nseq / KVNCH)
#define KV_STR  144
#define KV_TILE (64 * KV_STR)
#define KV_STG  (2 * KV_TILE)

__global__ __launch_bounds__(256, 2) void kv_mma_kernel(
    const __half* __restrict__ KH, const __half* __restrict__ VH,
    float* __restrict__ kv)
{
    __shared__ char smem[3 * KV_STG];
    const uint32_t sb = smem_u32(smem);

    const int bh = blockIdx.x;
    const int b = bh >> 4, h = bh & 15;
    const int chunk = blockIdx.y;
    const int tid = threadIdx.x;
    const int wid = tid >> 5;
    const int lane = tid & 31;
    const int warp_m = wid >> 1;
    const int warp_n = wid & 1;

    const size_t tokBase = (size_t)b * Nseq + (size_t)chunk * KVTOK;

    const int atr = (lane & 7) + ((lane >> 4) << 3);
    const int atc = ((lane >> 3) & 1) * 16;
    const int btr = (lane & 7) + ((lane >> 3) & 1) * 8;
    const int btc = (lane >> 4) * 16;

    float acc[4][4];
#pragma unroll
    for (int nt = 0; nt < 4; ++nt)
#pragma unroll
        for (int j = 0; j < 4; ++j) acc[nt][j] = 0.f;

    const int niter = KVTOK / 64;

    auto load_tile = [&](int s, int it) {
        const uint32_t stage = sb + (uint32_t)s * KV_STG;
#pragma unroll
        for (int i = 0; i < 4; ++i) {
            int idx = tid + i * 256;
            int tile = idx >> 9;
            int w = idx & 511;
            int row = w >> 3, cb = w & 7;
            const __half* gp = tile ? VH : KH;
            const void* ga = gp + (tokBase + (size_t)it * 64 + row) * EMBED + h * HDIM + cb * 8;
            uint32_t so = stage + (uint32_t)tile * KV_TILE + (uint32_t)row * KV_STR + cb * 16;
            CP_ASYNC16(so, ga);
        }
        CP_COMMIT();
    };

    load_tile(0, 0);
    load_tile(1, 1);

    for (int it = 0; it < niter; ++it) {
        if (it == niter - 1) { CP_WAIT(0); } else { CP_WAIT(1); }
        __syncthreads();

        if (it + 2 < niter)
            load_tile((it + 2) % 3, it + 2);

        const uint32_t st = sb + (uint32_t)(it % 3) * KV_STG;
        const uint32_t kb = st;
        const uint32_t vb = st + KV_TILE;

#pragma unroll
        for (int ts = 0; ts < 4; ++ts) {
            const int t0 = ts * 16;
            uint32_t a4[4];
            ldsm4t(a4, kb + (uint32_t)(t0 + atr) * KV_STR
                      + (uint32_t)(warp_m * 32) + atc);
            uint32_t br[4][2];
#pragma unroll
            for (int nt2 = 0; nt2 < 2; ++nt2) {
                uint32_t t4[4];
                ldsm4t(t4, vb + (uint32_t)(t0 + btr) * KV_STR
                          + (uint32_t)(warp_n * 64 + nt2 * 32) + btc);
                br[nt2*2][0]   = t4[0]; br[nt2*2][1]   = t4[1];
                br[nt2*2+1][0] = t4[2]; br[nt2*2+1][1] = t4[3];
            }
#pragma unroll
            for (int nt = 0; nt < 4; ++nt)
                mma16816(acc[nt], a4, br[nt]);
        }
    }

    float* kvp = kv + (size_t)bh * (HDIM * HDIM);
#pragma unroll
    for (int nt = 0; nt < 4; ++nt) {
#pragma unroll
        for (int hh = 0; hh < 2; ++hh) {
            const int d = warp_m * 16 + (lane >> 2) + hh * 8;
            const int e = warp_n * 32 + nt * 8 + (lane & 3) * 2;
            atomicAdd(kvp + d * HDIM + e,     acc[nt][hh * 2 + 0]);
            atomicAdd(kvp + d * HDIM + e + 1, acc[nt][hh * 2 + 1]);
        }
    }
}

// ---------------------------------------------------------------------------
// ksum: column sums of KH
// ---------------------------------------------------------------------------
__global__ __launch_bounds__(256) void ksum_kernel(
    const __half* __restrict__ KH, float* __restrict__ ksum)
{
    const int col = blockIdx.x * 256 + threadIdx.x;
    const int b = blockIdx.y;
    const int n0 = blockIdx.z * 1024;
    const __half* p = KH + ((size_t)b * Nseq + n0) * EMBED + col;
    float s0 = 0.f, s1 = 0.f, s2 = 0.f, s3 = 0.f;
#pragma unroll 4
    for (int r = 0; r < 1024; r += 4) {
        s0 += __half2float(p[(size_t)(r + 0) * EMBED]);
        s1 += __half2float(p[(size_t)(r + 1) * EMBED]);
        s2 += __half2float(p[(size_t)(r + 2) * EMBED]);
        s3 += __half2float(p[(size_t)(r + 3) * EMBED]);
    }
    const int bh = b * 16 + (col >> 6);
    const int d = col & 63;
    atomicAdd(ksum + bh * 64 + d, (s0 + s1) + (s2 + s3));
}

// ---------------------------------------------------------------------------
// kvT convert
// ---------------------------------------------------------------------------
__global__ __launch_bounds__(256) void kvT_cvt_kernel(
    const float* __restrict__ kv, __half* __restrict__ kvTh)
{
    const int bh = blockIdx.x;
    const int tid = threadIdx.x;
    __shared__ float s[64][65];
    for (int i = tid; i < 4096; i += 256)
        s[i >> 6][i & 63] = kv[(size_t)bh * 4096 + i];
    __syncthreads();
    for (int i = tid; i < 4096; i += 256) {
        const int e = i >> 6, d = i & 63;
        kvTh[(size_t)bh * 4096 + i] = __float2half(s[d][e]);
    }
}

// ---------------------------------------------------------------------------
// denom
// ---------------------------------------------------------------------------
__global__ __launch_bounds__(256) void denom_kernel(
    const __half* __restrict__ Qh, const float* __restrict__ ksum,
    float* __restrict__ dinv)
{
    const int bh = blockIdx.y;
    const int b = bh >> 4, h = bh & 15;
    const int tok = blockIdx.x * 256 + threadIdx.x;

    __shared__ float ks_s[64];
    if (threadIdx.x < 64) ks_s[threadIdx.x] = ksum[bh * 64 + threadIdx.x];
    __syncthreads();

    const __half2* qp = reinterpret_cast<const __half2*>(
        Qh + ((size_t)b * Nseq + tok) * EMBED + h * HDIM);
    float d = 0.f;
#pragma unroll
    for (int j = 0; j < 32; ++j) {
        float2 q2 = __half22float2(qp[j]);
        d = fmaf(q2.x, ks_s[2 * j], d);
        d = fmaf(q2.y, ks_s[2 * j + 1], d);
    }
    dinv[(size_t)bh * Nseq + tok] = 1.0f / (d + 1e-6f);
}

// ---------------------------------------------------------------------------
// attn numerator via MMA
// ---------------------------------------------------------------------------
#define AT_STR 144
__global__ __launch_bounds__(256) void attn_mma_kernel(
    const __half* __restrict__ Qh, const __half* __restrict__ kvTh,
    const float* __restrict__ dinv, __half* __restrict__ atH)
{
    __shared__ char smem[128 * AT_STR + 64 * AT_STR];
    const uint32_t sq = smem_u32(smem);
    const uint32_t skt = sq + 128 * AT_STR;

    const int bh = blockIdx.x;
    const int b = bh >> 4, h = bh & 15;
    const int tt = blockIdx.y;
    const int tid = threadIdx.x;
    const int wid = tid >> 5;
    const int lane = tid & 31;
    const int warp_m = wid >> 1;
    const int warp_n = wid & 1;

#pragma unroll
    for (int i = 0; i < 4; ++i) {
        int idx = tid + i * 256;
        int row = idx >> 3, cb = idx & 7;
        const void* ga = Qh + ((size_t)b * Nseq + tt * 128 + row) * EMBED + h * HDIM + cb * 8;
        CP_ASYNC16(sq + (uint32_t)row * AT_STR + cb * 16, ga);
    }
#pragma unroll
    for (int i = 0; i < 2; ++i) {
        int idx = tid + i * 256;
        int row = idx >> 3, cb = idx & 7;
        const void* ga = kvTh + (size_t)bh * 4096 + row * 64 + cb * 8;
        CP_ASYNC16(skt + (uint32_t)row * AT_STR + cb * 16, ga);
    }
    CP_COMMIT();
    CP_WAIT(0);
    __syncthreads();

    const int a_r = lane & 15;
    const int a_c = (lane >> 4) * 8;
    const int b_n = ((lane >> 4) << 3) + (lane & 7);
    const int b_k = ((lane >> 3) & 1) * 8;

    float acc[2][4][4];
#pragma unroll
    for (int mt = 0; mt < 2; ++mt)
#pragma unroll
        for (int nt = 0; nt < 4; ++nt)
#pragma unroll
            for (int j = 0; j < 4; ++j) acc[mt][nt][j] = 0.f;

#pragma unroll
    for (int ks = 0; ks < 4; ++ks) {
        const int k0 = ks * 16;
        uint32_t ar[2][4];
#pragma unroll
        for (int mt = 0; mt < 2; ++mt) {
            uint32_t off = (uint32_t)(warp_m * 32 + mt * 16 + a_r) * AT_STR
                         + (uint32_t)(k0 + a_c) * 2;
            ldsm4(ar[mt], sq + off);
        }
        uint32_t br[4][2];
#pragma unroll
        for (int nt2 = 0; nt2 < 2; ++nt2) {
            uint32_t off = (uint32_t)(warp_n * 32 + nt2 * 16 + b_n) * AT_STR
                         + (uint32_t)(k0 + b_k) * 2;
            uint32_t t4[4];
            ldsm4(t4, skt + off);
            br[nt2*2][0] = t4[0]; br[nt2*2][1] = t4[1];
            br[nt2*2+1][0] = t4[2]; br[nt2*2+1][1] = t4[3];
        }
#pragma unroll
        for (int mt = 0; mt < 2; ++mt)
#pragma unroll
            for (int nt = 0; nt < 4; ++nt)
                mma16816(acc[mt][nt], ar[mt], br[nt]);
    }

#pragma unroll
    for (int mt = 0; mt < 2; ++mt) {
#pragma unroll
        for (int hh = 0; hh < 2; ++hh) {
            const int rloc = warp_m * 32 + mt * 16 + (lane >> 2) + hh * 8;
            const float dv = __ldg(dinv + (size_t)bh * Nseq + tt * 128 + rloc);
            const size_t ob = ((size_t)b * Nseq + tt * 128 + rloc) * EMBED + h * HDIM;
#pragma unroll
            for (int nt = 0; nt < 4; ++nt) {
                const int col = warp_n * 32 + nt * 8 + (lane & 3) * 2;
                float f0 = acc[mt][nt][hh * 2 + 0] * dv;
                float f1 = acc[mt][nt][hh * 2 + 1] * dv;
                *reinterpret_cast<__half2*>(atH + ob + col) = __floats2half2_rn(f0, f1);
            }
        }
    }
}

// ---------------------------------------------------------------------------
// launch
// ---------------------------------------------------------------------------
extern "C" void kernel_launch(void* const* d_in, const int* in_sizes, int n_in,
                              void* d_out, int out_size)
{
    const float* query   = (const float*)d_in[0];
    const float* key_    = (const float*)d_in[1];
    const float* value   = (const float*)d_in[2];
    const float* Wq_down = (const float*)d_in[3];
    const float* Wq_up   = (const float*)d_in[4];
    const float* bq_up   = (const float*)d_in[5];
    const float* Wk_down = (const float*)d_in[6];
    const float* Wk_up   = (const float*)d_in[7];
    const float* bk_up   = (const float*)d_in[8];
    const float* Wv_down = (const float*)d_in[9];
    const float* Wv_up   = (const float*)d_in[10];
    const float* bv_up   = (const float*)d_in[11];
    const float* Wo      = (const float*)d_in[12];
    const float* bo      = (const float*)d_in[13];
    float* out = (float*)d_out;

    __half *QH, *KH, *VH, *atH, *kvTh;
    float *KVKS, *DINV;
    cudaGetSymbolAddress((void**)&QH,   g_QH);
    cudaGetSymbolAddress((void**)&KH,   g_KH);
    cudaGetSymbolAddress((void**)&VH,   g_VH);
    cudaGetSymbolAddress((void**)&atH,  g_atH);
    cudaGetSymbolAddress((void**)&kvTh, g_kvTh);
    cudaGetSymbolAddress((void**)&KVKS, g_kvks);
    cudaGetSymbolAddress((void**)&DINV, g_dinv);
    float* KV = KVKS;
    float* KS = KVKS + KV_ELEMS;

    cudaFuncSetAttribute((const void*)gemm_fused<0>, cudaFuncAttributeMaxDynamicSharedMemorySize, SMEM_GEMM);
    cudaFuncSetAttribute((const void*)gemm_fused<1>, cudaFuncAttributeMaxDynamicSharedMemorySize, SMEM_GEMM);
    cudaFuncSetAttribute((const void*)gemm_fused<2>, cudaFuncAttributeMaxDynamicSharedMemorySize, SMEM_GEMM);

    const dim3 blk(256);
    const dim3 gblk(512);

    // converts (2 launches)
    wcvt_kernel<<<(6 * WSEG4 + EMBED*EMBED/4 + 255) / 256, blk>>>(
        Wq_down, Wq_up, Wk_down, Wk_up, Wv_down, Wv_up, Wo);
    cvt3_kernel<<<dim3(MTOK * EMBED / 8 / 256, 3), blk>>>(query, key_, value);

    // down projections (one launch, z = q/k/v)
    gemm_fused<0><<<dim3(RANK / 128, MTOK / 256, 3), gblk, SMEM_GEMM>>>(
        nullptr, nullptr, nullptr, nullptr);
    // up projections (one launch, z = q/k/v; elu for q,k)
    gemm_fused<1><<<dim3(EMBED / 128, MTOK / 256, 3), gblk, SMEM_GEMM>>>(
        bq_up, bk_up, bv_up, nullptr);

    // kv (MMA) / ksum
    const int nz = KV_ELEMS + KS_ELEMS;
    zero_kernel<<<(nz + 255) / 256, blk>>>(KVKS, nz);
    kv_mma_kernel<<<dim3(BH, KVNCH), blk>>>(KH, VH, KV);
    ksum_kernel<<<dim3(EMBED / 256, Bv, Nseq / 1024), blk>>>(KH, KS);
    kvT_cvt_kernel<<<BH, blk>>>(KV, kvTh);
    denom_kernel<<<dim3(Nseq / 256, BH), blk>>>(QH, KS, DINV);

    // attention numerator (MMA) + divide
    attn_mma_kernel<<<dim3(BH, Nseq / 128), blk>>>(QH, kvTh, DINV, atH);

    // output projection (fp32 out)
    gemm_fused<2><<<dim3(EMBED / 128, MTOK / 256, 1), gblk, SMEM_GEMM>>>(
        bo, nullptr, nullptr, out);
}

// round 13
// speedup vs baseline: 1.1267x; 1.1267x over previous
#include <cuda_runtime.h>
#include <cuda_fp16.h>
#include <cstdint>

// ---------------------------------------------------------------------------
// Problem constants
// ---------------------------------------------------------------------------
#define Bv     4
#define Nseq   8192
#define EMBED  1024
#define HEADS  16
#define HDIM   64
#define RANK   512
#define MTOK   (Bv * Nseq)          // 32768
#define BH     (Bv * HEADS)         // 64

// ---------------------------------------------------------------------------
// Scratch (__device__ globals; allocation forbidden)
// ---------------------------------------------------------------------------
__device__ __half g_inH3[(size_t)3 * MTOK * EMBED];
__device__ __half g_yH3 [(size_t)3 * MTOK * RANK];
__device__ __half g_QH [MTOK * EMBED];
__device__ __half g_KH [MTOK * EMBED];
__device__ __half g_VH [MTOK * EMBED];
__device__ __half g_atH[MTOK * EMBED];

#define W_QD 0
#define W_QU (W_QD + RANK*EMBED)
#define W_KD (W_QU + EMBED*RANK)
#define W_KU (W_KD + RANK*EMBED)
#define W_VD (W_KU + EMBED*RANK)
#define W_VU (W_VD + RANK*EMBED)
#define W_O  (W_VU + EMBED*RANK)
#define W_TOT (W_O + EMBED*EMBED)
__device__ __half g_wH[W_TOT];

#define KV_ELEMS (BH * HDIM * HDIM)
#define KS_ELEMS (BH * HDIM)
__device__ float  g_kvks[KV_ELEMS + KS_ELEMS];
__device__ __half g_kvTh[KV_ELEMS];

// ---------------------------------------------------------------------------
// helpers
// ---------------------------------------------------------------------------
__device__ __forceinline__ uint32_t smem_u32(const void* p) {
    uint32_t a;
    asm("{ .reg .u64 t; cvta.to.shared.u64 t, %1; cvt.u32.u64 %0, t; }"
        : "=r"(a) : "l"(p));
    return a;
}

__device__ __forceinline__ void ldsm4(uint32_t* r, uint32_t addr) {
    asm volatile("ldmatrix.sync.aligned.m8n8.x4.shared.b16 {%0,%1,%2,%3}, [%4];"
        : "=r"(r[0]), "=r"(r[1]), "=r"(r[2]), "=r"(r[3]) : "r"(addr));
}

__device__ __forceinline__ void ldsm4t(uint32_t* r, uint32_t addr) {
    asm volatile("ldmatrix.sync.aligned.m8n8.x4.trans.shared.b16 {%0,%1,%2,%3}, [%4];"
        : "=r"(r[0]), "=r"(r[1]), "=r"(r[2]), "=r"(r[3]) : "r"(addr));
}

__device__ __forceinline__ void mma16816(float* c, const uint32_t* a, const uint32_t* b) {
    asm volatile("mma.sync.aligned.m16n8k16.row.col.f32.f16.f16.f32 "
        "{%0,%1,%2,%3}, {%4,%5,%6,%7}, {%8,%9}, {%0,%1,%2,%3};"
        : "+f"(c[0]), "+f"(c[1]), "+f"(c[2]), "+f"(c[3])
        : "r"(a[0]), "r"(a[1]), "r"(a[2]), "r"(a[3]), "r"(b[0]), "r"(b[1]));
}

#define CP_ASYNC16(so, ga) \
    asm volatile("cp.async.cg.shared.global [%0], [%1], 16;\n" :: "r"(so), "l"(ga))
#define CP_COMMIT() asm volatile("cp.async.commit_group;\n" ::: "memory")
#define CP_WAIT(n)  asm volatile("cp.async.wait_group %0;\n" :: "n"(n) : "memory")

// ---------------------------------------------------------------------------
// cvt3: q/k/v fp32 -> fp16, one launch
// ---------------------------------------------------------------------------
__global__ void cvt3_kernel(const float* __restrict__ x0,
                            const float* __restrict__ x1,
                            const float* __restrict__ x2)
{
    const int z = blockIdx.y;
    const float* x = (z == 0) ? x0 : (z == 1) ? x1 : x2;
    __half* dst = g_inH3 + (size_t)z * (MTOK * EMBED);
    const int i = blockIdx.x * 256 + threadIdx.x;
    const float4* xp = reinterpret_cast<const float4*>(x) + 2 * (size_t)i;
    float4 a = xp[0], b = xp[1];
    __half2* yp = reinterpret_cast<__half2*>(dst) + 4 * (size_t)i;
    yp[0] = __floats2half2_rn(a.x, a.y);
    yp[1] = __floats2half2_rn(a.z, a.w);
    yp[2] = __floats2half2_rn(b.x, b.y);
    yp[3] = __floats2half2_rn(b.z, b.w);
}

// ---------------------------------------------------------------------------
// wcvt: all 7 weights fp32 -> fp16 in one launch
// ---------------------------------------------------------------------------
#define WSEG4 (RANK * EMBED / 4)
__global__ void wcvt_kernel(const float* __restrict__ p0, const float* __restrict__ p1,
                            const float* __restrict__ p2, const float* __restrict__ p3,
                            const float* __restrict__ p4, const float* __restrict__ p5,
                            const float* __restrict__ p6)
{
    const int i = blockIdx.x * 256 + threadIdx.x;
    int seg, off;
    if (i >= 6 * WSEG4) { seg = 6; off = i - 6 * WSEG4; }
    else                { seg = i / WSEG4; off = i % WSEG4; }
    const float* ps[7] = {p0, p1, p2, p3, p4, p5, p6};
    float4 v = reinterpret_cast<const float4*>(ps[seg])[off];
    __half2* yp = reinterpret_cast<__half2*>(g_wH) + 2 * (size_t)i;
    yp[0] = __floats2half2_rn(v.x, v.y);
    yp[1] = __floats2half2_rn(v.z, v.w);
}

// ---------------------------------------------------------------------------
// fused mma.sync fp16 NT GEMM. Tile 128x128, BK=64, 8 warps, 3-stage, 2 CTA/SM.
// KIND 0: down3. KIND 1: up3 (bias, elu for z<2). KIND 2: Wo (fp32 + bias)
// ---------------------------------------------------------------------------
#define BKC        64
#define RSTRIDE_B  144
#define A_TILE_BY  (128 * RSTRIDE_B)
#define B_TILE_BY  (128 * RSTRIDE_B)
#define STAGE_BY   (A_TILE_BY + B_TILE_BY)
#define NSTAGE     3
#define SMEM_GEMM  (NSTAGE * STAGE_BY)      // 110592
#define OFF_A      0
#define OFF_B      A_TILE_BY

__device__ __forceinline__ void load_stage_mma(
    uint32_t sb, int tid, int s, int k0,
    const __half* __restrict__ A, const __half* __restrict__ B,
    int K, int aRow0, int bRow0)
{
    const uint32_t stage = sb + (uint32_t)s * STAGE_BY;
#pragma unroll
    for (int i = 0; i < 8; ++i) {
        int idx = tid + i * 256;
        int row = (idx & 1023) >> 3;
        int cb  = idx & 7;
        const __half* gp;
        int r0;
        uint32_t tbase;
        if (idx < 1024) { gp = A; r0 = aRow0; tbase = OFF_A; }
        else            { gp = B; r0 = bRow0; tbase = OFF_B; }
        const void* ga = gp + (size_t)(r0 + row) * K + k0 + cb * 8;
        uint32_t so = stage + tbase + (uint32_t)row * RSTRIDE_B + cb * 16;
        CP_ASYNC16(so, ga);
    }
    CP_COMMIT();
}

template <int KIND>
__global__ __launch_bounds__(256, 2) void gemm_fused(
    const float* __restrict__ b0, const float* __restrict__ b1,
    const float* __restrict__ b2, float* __restrict__ outF)
{
    constexpr int NN = (KIND == 0) ? RANK : EMBED;
    constexpr int KK = (KIND == 0) ? EMBED : ((KIND == 1) ? RANK : EMBED);

    extern __shared__ char smem[];
    const uint32_t sb = smem_u32(smem);
    const int tid = threadIdx.x;
    const int wid = tid >> 5;
    const int lane = tid & 31;
    const int bn = blockIdx.x, bm = blockIdx.y;
    const int z = (KIND == 2) ? 0 : blockIdx.z;
    const int warp_m = wid >> 2;
    const int warp_n = wid & 3;
    const int aRow0 = bm * 128, bRow0 = bn * 128;

    const __half* A;
    const __half* B;
    __half* Ch = nullptr;
    const float* bias = nullptr;
    bool elu = false;
    if (KIND == 0) {
        A = g_inH3 + (size_t)z * (MTOK * EMBED);
        B = g_wH + (size_t)z * (2 * RANK * EMBED);
        Ch = g_yH3 + (size_t)z * (MTOK * RANK);
    } else if (KIND == 1) {
        A = g_yH3 + (size_t)z * (MTOK * RANK);
        B = g_wH + W_QU + (size_t)z * (2 * RANK * EMBED);
        bias = (z == 0) ? b0 : (z == 1) ? b1 : b2;
        Ch = (z == 0) ? g_QH : (z == 1) ? g_KH : g_VH;
        elu = (z < 2);
    } else {
        A = g_atH;
        B = g_wH + W_O;
        bias = b0;
    }

    float acc[4][4][4];
#pragma unroll
    for (int mt = 0; mt < 4; ++mt)
#pragma unroll
        for (int nt = 0; nt < 4; ++nt)
#pragma unroll
            for (int j = 0; j < 4; ++j) acc[mt][nt][j] = 0.f;

    const int nch = KK / BKC;

    load_stage_mma(sb, tid, 0, 0,   A, B, KK, aRow0, bRow0);
    load_stage_mma(sb, tid, 1, BKC, A, B, KK, aRow0, bRow0);

    const int a_r = lane & 15;
    const int a_c = (lane >> 4) * 8;
    const int b_n = ((lane >> 4) << 3) + (lane & 7);
    const int b_k = ((lane >> 3) & 1) * 8;

    for (int c = 0; c < nch; ++c) {
        if (c == nch - 1) { CP_WAIT(0); } else { CP_WAIT(1); }
        __syncthreads();

        if (c + 2 < nch)
            load_stage_mma(sb, tid, (c + 2) % NSTAGE, (c + 2) * BKC,
                           A, B, KK, aRow0, bRow0);

        const uint32_t st = sb + (uint32_t)(c % NSTAGE) * STAGE_BY;
#pragma unroll
        for (int ks = 0; ks < 4; ++ks) {
            const int k0 = ks * 16;
            uint32_t ar[4][4];
#pragma unroll
            for (int mt = 0; mt < 4; ++mt) {
                uint32_t off = (uint32_t)(warp_m * 64 + mt * 16 + a_r) * RSTRIDE_B
                             + (uint32_t)(k0 + a_c) * 2;
                ldsm4(ar[mt], st + OFF_A + off);
            }
            uint32_t br[4][2];
#pragma unroll
            for (int nt2 = 0; nt2 < 2; ++nt2) {
                uint32_t off = (uint32_t)(warp_n * 32 + nt2 * 16 + b_n) * RSTRIDE_B
                             + (uint32_t)(k0 + b_k) * 2;
                uint32_t t4[4];
                ldsm4(t4, st + OFF_B + off);
                br[nt2*2][0] = t4[0]; br[nt2*2][1] = t4[1];
                br[nt2*2+1][0] = t4[2]; br[nt2*2+1][1] = t4[3];
            }
#pragma unroll
            for (int mt = 0; mt < 4; ++mt)
#pragma unroll
                for (int nt = 0; nt < 4; ++nt)
                    mma16816(acc[mt][nt], ar[mt], br[nt]);
        }
    }

    // epilogue
#pragma unroll
    for (int mt = 0; mt < 4; ++mt) {
#pragma unroll
        for (int nt = 0; nt < 4; ++nt) {
            const int row0 = bm * 128 + warp_m * 64 + mt * 16 + (lane >> 2);
            const int col  = bn * 128 + warp_n * 32 + nt * 8 + (lane & 3) * 2;
#pragma unroll
            for (int h = 0; h < 2; ++h) {
                const int row = row0 + h * 8;
                float f0 = acc[mt][nt][h * 2 + 0];
                float f1 = acc[mt][nt][h * 2 + 1];
                if (KIND >= 1) {
                    f0 += __ldg(bias + col);
                    f1 += __ldg(bias + col + 1);
                }
                if (KIND == 1 && elu) {
                    f0 = (f0 > 0.f) ? (f0 + 1.f) : __expf(f0);
                    f1 = (f1 > 0.f) ? (f1 + 1.f) : __expf(f1);
                }
                if (KIND == 2) {
                    *reinterpret_cast<float2*>(outF + (size_t)row * NN + col) =
                        make_float2(f0, f1);
                } else {
                    *reinterpret_cast<__half2*>(Ch + (size_t)row * NN + col) =
                        __floats2half2_rn(f0, f1);
                }
            }
        }
    }
}

// ---------------------------------------------------------------------------
// zero kernel
// ---------------------------------------------------------------------------
__global__ void zero_kernel(float* __restrict__ p, int n)
{
    int i = blockIdx.x * blockDim.x + threadIdx.x;
    if (i < n) p[i] = 0.f;
}

// ---------------------------------------------------------------------------
// kv via MMA: kv[bh][d][e] += sum_n k[n,d]*v[n,e]
// ---------------------------------------------------------------------------
#define KVNCH   4
#define KVTOK   (Nseq / KVNCH)
#define KV_STR  144
#define KV_TILE (64 * KV_STR)
#define KV_STG  (2 * KV_TILE)

__global__ __launch_bounds__(256, 2) void kv_mma_kernel(
    const __half* __restrict__ KH, const __half* __restrict__ VH,
    float* __restrict__ kv)
{
    __shared__ char smem[3 * KV_STG];
    const uint32_t sb = smem_u32(smem);

    const int bh = blockIdx.x;
    const int b = bh >> 4, h = bh & 15;
    const int chunk = blockIdx.y;
    const int tid = threadIdx.x;
    const int wid = tid >> 5;
    const int lane = tid & 31;
    const int warp_m = wid >> 1;
    const int warp_n = wid & 1;

    const size_t tokBase = (size_t)b * Nseq + (size_t)chunk * KVTOK;

    const int atr = (lane & 7) + ((lane >> 4) << 3);
    const int atc = ((lane >> 3) & 1) * 16;
    const int btr = (lane & 7) + ((lane >> 3) & 1) * 8;
    const int btc = (lane >> 4) * 16;

    float acc[4][4];
#pragma unroll
    for (int nt = 0; nt < 4; ++nt)
#pragma unroll
        for (int j = 0; j < 4; ++j) acc[nt][j] = 0.f;

    const int niter = KVTOK / 64;

    auto load_tile = [&](int s, int it) {
        const uint32_t stage = sb + (uint32_t)s * KV_STG;
#pragma unroll
        for (int i = 0; i < 4; ++i) {
            int idx = tid + i * 256;
            int tile = idx >> 9;
            int w = idx & 511;
            int row = w >> 3, cb = w & 7;
            const __half* gp = tile ? VH : KH;
            const void* ga = gp + (tokBase + (size_t)it * 64 + row) * EMBED + h * HDIM + cb * 8;
            uint32_t so = stage + (uint32_t)tile * KV_TILE + (uint32_t)row * KV_STR + cb * 16;
            CP_ASYNC16(so, ga);
        }
        CP_COMMIT();
    };

    load_tile(0, 0);
    load_tile(1, 1);

    for (int it = 0; it < niter; ++it) {
        if (it == niter - 1) { CP_WAIT(0); } else { CP_WAIT(1); }
        __syncthreads();

        if (it + 2 < niter)
            load_tile((it + 2) % 3, it + 2);

        const uint32_t st = sb + (uint32_t)(it % 3) * KV_STG;
        const uint32_t kb = st;
        const uint32_t vb = st + KV_TILE;

#pragma unroll
        for (int ts = 0; ts < 4; ++ts) {
            const int t0 = ts * 16;
            uint32_t a4[4];
            ldsm4t(a4, kb + (uint32_t)(t0 + atr) * KV_STR
                      + (uint32_t)(warp_m * 32) + atc);
            uint32_t br[4][2];
#pragma unroll
            for (int nt2 = 0; nt2 < 2; ++nt2) {
                uint32_t t4[4];
                ldsm4t(t4, vb + (uint32_t)(t0 + btr) * KV_STR
                          + (uint32_t)(warp_n * 64 + nt2 * 32) + btc);
                br[nt2*2][0]   = t4[0]; br[nt2*2][1]   = t4[1];
                br[nt2*2+1][0] = t4[2]; br[nt2*2+1][1] = t4[3];
            }
#pragma unroll
            for (int nt = 0; nt < 4; ++nt)
                mma16816(acc[nt], a4, br[nt]);
        }
    }

    float* kvp = kv + (size_t)bh * (HDIM * HDIM);
#pragma unroll
    for (int nt = 0; nt < 4; ++nt) {
#pragma unroll
        for (int hh = 0; hh < 2; ++hh) {
            const int d = warp_m * 16 + (lane >> 2) + hh * 8;
            const int e = warp_n * 32 + nt * 8 + (lane & 3) * 2;
            atomicAdd(kvp + d * HDIM + e,     acc[nt][hh * 2 + 0]);
            atomicAdd(kvp + d * HDIM + e + 1, acc[nt][hh * 2 + 1]);
        }
    }
}

// ---------------------------------------------------------------------------
// ksum: column sums of KH
// ---------------------------------------------------------------------------
__global__ __launch_bounds__(256) void ksum_kernel(
    const __half* __restrict__ KH, float* __restrict__ ksum)
{
    const int col = blockIdx.x * 256 + threadIdx.x;
    const int b = blockIdx.y;
    const int n0 = blockIdx.z * 1024;
    const __half* p = KH + ((size_t)b * Nseq + n0) * EMBED + col;
    float s0 = 0.f, s1 = 0.f, s2 = 0.f, s3 = 0.f;
#pragma unroll 4
    for (int r = 0; r < 1024; r += 4) {
        s0 += __half2float(p[(size_t)(r + 0) * EMBED]);
        s1 += __half2float(p[(size_t)(r + 1) * EMBED]);
        s2 += __half2float(p[(size_t)(r + 2) * EMBED]);
        s3 += __half2float(p[(size_t)(r + 3) * EMBED]);
    }
    const int bh = b * 16 + (col >> 6);
    const int d = col & 63;
    atomicAdd(ksum + bh * 64 + d, (s0 + s1) + (s2 + s3));
}

// ---------------------------------------------------------------------------
// kvT convert
// ---------------------------------------------------------------------------
__global__ __launch_bounds__(256) void kvT_cvt_kernel(
    const float* __restrict__ kv, __half* __restrict__ kvTh)
{
    const int bh = blockIdx.x;
    const int tid = threadIdx.x;
    __shared__ float s[64][65];
    for (int i = tid; i < 4096; i += 256)
        s[i >> 6][i & 63] = kv[(size_t)bh * 4096 + i];
    __syncthreads();
    for (int i = tid; i < 4096; i += 256) {
        const int e = i >> 6, d = i & 63;
        kvTh[(size_t)bh * 4096 + i] = __float2half(s[d][e]);
    }
}

// ---------------------------------------------------------------------------
// attn numerator via MMA + fused denominator
// atH = (Q @ kvT^T) / (Q . ksum + 1e-6)
// ---------------------------------------------------------------------------
#define AT_STR 144
__global__ __launch_bounds__(256) void attn_mma_kernel(
    const __half* __restrict__ Qh, const __half* __restrict__ kvTh,
    const float* __restrict__ ksum, __half* __restrict__ atH)
{
    __shared__ char smem[128 * AT_STR + 64 * AT_STR];
    __shared__ float ks_s[64];
    __shared__ float dinv_s[128];
    const uint32_t sq = smem_u32(smem);
    const uint32_t skt = sq + 128 * AT_STR;

    const int bh = blockIdx.x;
    const int b = bh >> 4, h = bh & 15;
    const int tt = blockIdx.y;
    const int tid = threadIdx.x;
    const int wid = tid >> 5;
    const int lane = tid & 31;
    const int warp_m = wid >> 1;
    const int warp_n = wid & 1;

#pragma unroll
    for (int i = 0; i < 4; ++i) {
        int idx = tid + i * 256;
        int row = idx >> 3, cb = idx & 7;
        const void* ga = Qh + ((size_t)b * Nseq + tt * 128 + row) * EMBED + h * HDIM + cb * 8;
        CP_ASYNC16(sq + (uint32_t)row * AT_STR + cb * 16, ga);
    }
#pragma unroll
    for (int i = 0; i < 2; ++i) {
        int idx = tid + i * 256;
        int row = idx >> 3, cb = idx & 7;
        const void* ga = kvTh + (size_t)bh * 4096 + row * 64 + cb * 8;
        CP_ASYNC16(skt + (uint32_t)row * AT_STR + cb * 16, ga);
    }
    if (tid < 64) ks_s[tid] = ksum[bh * 64 + tid];
    CP_COMMIT();
    CP_WAIT(0);
    __syncthreads();

    // fused denominator: threads 0..127 compute token dots from smem Q
    if (tid < 128) {
        const uint32_t qrow = sq + (uint32_t)tid * AT_STR;
        float d = 0.f;
#pragma unroll
        for (int j = 0; j < 32; ++j) {
            uint32_t packed;
            asm volatile("ld.shared.b32 %0, [%1];" : "=r"(packed) : "r"(qrow + j * 4));
            __half2 q2 = *reinterpret_cast<__half2*>(&packed);
            float2 qf = __half22float2(q2);
            d = fmaf(qf.x, ks_s[2 * j], d);
            d = fmaf(qf.y, ks_s[2 * j + 1], d);
        }
        dinv_s[tid] = 1.0f / (d + 1e-6f);
    }
    __syncthreads();

    const int a_r = lane & 15;
    const int a_c = (lane >> 4) * 8;
    const int b_n = ((lane >> 4) << 3) + (lane & 7);
    const int b_k = ((lane >> 3) & 1) * 8;

    float acc[2][4][4];
#pragma unroll
    for (int mt = 0; mt < 2; ++mt)
#pragma unroll
        for (int nt = 0; nt < 4; ++nt)
#pragma unroll
            for (int j = 0; j < 4; ++j) acc[mt][nt][j] = 0.f;

#pragma unroll
    for (int ks = 0; ks < 4; ++ks) {
        const int k0 = ks * 16;
        uint32_t ar[2][4];
#pragma unroll
        for (int mt = 0; mt < 2; ++mt) {
            uint32_t off = (uint32_t)(warp_m * 32 + mt * 16 + a_r) * AT_STR
                         + (uint32_t)(k0 + a_c) * 2;
            ldsm4(ar[mt], sq + off);
        }
        uint32_t br[4][2];
#pragma unroll
        for (int nt2 = 0; nt2 < 2; ++nt2) {
            uint32_t off = (uint32_t)(warp_n * 32 + nt2 * 16 + b_n) * AT_STR
                         + (uint32_t)(k0 + b_k) * 2;
            uint32_t t4[4];
            ldsm4(t4, skt + off);
            br[nt2*2][0] = t4[0]; br[nt2*2][1] = t4[1];
            br[nt2*2+1][0] = t4[2]; br[nt2*2+1][1] = t4[3];
        }
#pragma unroll
        for (int mt = 0; mt < 2; ++mt)
#pragma unroll
            for (int nt = 0; nt < 4; ++nt)
                mma16816(acc[mt][nt], ar[mt], br[nt]);
    }

#pragma unroll
    for (int mt = 0; mt < 2; ++mt) {
#pragma unroll
        for (int hh = 0; hh < 2; ++hh) {
            const int rloc = warp_m * 32 + mt * 16 + (lane >> 2) + hh * 8;
            const float dv = dinv_s[rloc];
            const size_t ob = ((size_t)b * Nseq + tt * 128 + rloc) * EMBED + h * HDIM;
#pragma unroll
            for (int nt = 0; nt < 4; ++nt) {
                const int col = warp_n * 32 + nt * 8 + (lane & 3) * 2;
                float f0 = acc[mt][nt][hh * 2 + 0] * dv;
                float f1 = acc[mt][nt][hh * 2 + 1] * dv;
                *reinterpret_cast<__half2*>(atH + ob + col) = __floats2half2_rn(f0, f1);
            }
        }
    }
}

// ---------------------------------------------------------------------------
// launch
// ---------------------------------------------------------------------------
extern "C" void kernel_launch(void* const* d_in, const int* in_sizes, int n_in,
                              void* d_out, int out_size)
{
    const float* query   = (const float*)d_in[0];
    const float* key_    = (const float*)d_in[1];
    const float* value   = (const float*)d_in[2];
    const float* Wq_down = (const float*)d_in[3];
    const float* Wq_up   = (const float*)d_in[4];
    const float* bq_up   = (const float*)d_in[5];
    const float* Wk_down = (const float*)d_in[6];
    const float* Wk_up   = (const float*)d_in[7];
    const float* bk_up   = (const float*)d_in[8];
    const float* Wv_down = (const float*)d_in[9];
    const float* Wv_up   = (const float*)d_in[10];
    const float* bv_up   = (const float*)d_in[11];
    const float* Wo      = (const float*)d_in[12];
    const float* bo      = (const float*)d_in[13];
    float* out = (float*)d_out;

    __half *QH, *KH, *VH, *atH, *kvTh;
    float *KVKS;
    cudaGetSymbolAddress((void**)&QH,   g_QH);
    cudaGetSymbolAddress((void**)&KH,   g_KH);
    cudaGetSymbolAddress((void**)&VH,   g_VH);
    cudaGetSymbolAddress((void**)&atH,  g_atH);
    cudaGetSymbolAddress((void**)&kvTh, g_kvTh);
    cudaGetSymbolAddress((void**)&KVKS, g_kvks);
    float* KV = KVKS;
    float* KS = KVKS + KV_ELEMS;

    cudaFuncSetAttribute((const void*)gemm_fused<0>, cudaFuncAttributeMaxDynamicSharedMemorySize, SMEM_GEMM);
    cudaFuncSetAttribute((const void*)gemm_fused<1>, cudaFuncAttributeMaxDynamicSharedMemorySize, SMEM_GEMM);
    cudaFuncSetAttribute((const void*)gemm_fused<2>, cudaFuncAttributeMaxDynamicSharedMemorySize, SMEM_GEMM);

    const dim3 blk(256);

    // converts (2 launches)
    wcvt_kernel<<<(6 * WSEG4 + EMBED*EMBED/4 + 255) / 256, blk>>>(
        Wq_down, Wq_up, Wk_down, Wk_up, Wv_down, Wv_up, Wo);
    cvt3_kernel<<<dim3(MTOK * EMBED / 8 / 256, 3), blk>>>(query, key_, value);

    // down projections (one launch, z = q/k/v)
    gemm_fused<0><<<dim3(RANK / 128, MTOK / 128, 3), blk, SMEM_GEMM>>>(
        nullptr, nullptr, nullptr, nullptr);
    // up projections (one launch, z = q/k/v; elu for q,k)
    gemm_fused<1><<<dim3(EMBED / 128, MTOK / 128, 3), blk, SMEM_GEMM>>>(
        bq_up, bk_up, bv_up, nullptr);

    // kv (MMA) / ksum
    const int nz = KV_ELEMS + KS_ELEMS;
    zero_kernel<<<(nz + 255) / 256, blk>>>(KVKS, nz);
    kv_mma_kernel<<<dim3(BH, KVNCH), blk>>>(KH, VH, KV);
    ksum_kernel<<<dim3(EMBED / 256, Bv, Nseq / 1024), blk>>>(KH, KS);
    kvT_cvt_kernel<<<BH, blk>>>(KV, kvTh);

    // attention numerator (MMA) + fused denom + divide
    attn_mma_kernel<<<dim3(BH, Nseq / 128), blk>>>(QH, kvTh, KS, atH);

    // output projection (fp32 out)
    gemm_fused<2><<<dim3(EMBED / 128, MTOK / 128, 1), blk, SMEM_GEMM>>>(
        bo, nullptr, nullptr, out);
}

// round 14
// speedup vs baseline: 1.1508x; 1.0214x over previous
#include <cuda_runtime.h>
#include <cuda_fp16.h>
#include <cstdint>

// ---------------------------------------------------------------------------
// Problem constants
// ---------------------------------------------------------------------------
#define Bv     4
#define Nseq   8192
#define EMBED  1024
#define HEADS  16
#define HDIM   64
#define RANK   512
#define MTOK   (Bv * Nseq)          // 32768
#define BH     (Bv * HEADS)         // 64

// ---------------------------------------------------------------------------
// Scratch (__device__ globals; allocation forbidden)
// ---------------------------------------------------------------------------
__device__ __half g_inH3[(size_t)3 * MTOK * EMBED];
__device__ __half g_yH3 [(size_t)3 * MTOK * RANK];
__device__ __half g_QH [MTOK * EMBED];
__device__ __half g_KH [MTOK * EMBED];
__device__ __half g_VH [MTOK * EMBED];
__device__ __half g_atH[MTOK * EMBED];

#define W_QD 0
#define W_QU (W_QD + RANK*EMBED)
#define W_KD (W_QU + EMBED*RANK)
#define W_KU (W_KD + RANK*EMBED)
#define W_VD (W_KU + EMBED*RANK)
#define W_VU (W_VD + RANK*EMBED)
#define W_O  (W_VU + EMBED*RANK)
#define W_TOT (W_O + EMBED*EMBED)
__device__ __half g_wH[W_TOT];

#define KV_ELEMS (BH * HDIM * HDIM)
#define KS_ELEMS (BH * HDIM)
__device__ float  g_kvks[KV_ELEMS + KS_ELEMS];
__device__ __half g_kvTh[KV_ELEMS];

// ---------------------------------------------------------------------------
// helpers
// ---------------------------------------------------------------------------
__device__ __forceinline__ uint32_t smem_u32(const void* p) {
    uint32_t a;
    asm("{ .reg .u64 t; cvta.to.shared.u64 t, %1; cvt.u32.u64 %0, t; }"
        : "=r"(a) : "l"(p));
    return a;
}

__device__ __forceinline__ void ldsm4(uint32_t* r, uint32_t addr) {
    asm volatile("ldmatrix.sync.aligned.m8n8.x4.shared.b16 {%0,%1,%2,%3}, [%4];"
        : "=r"(r[0]), "=r"(r[1]), "=r"(r[2]), "=r"(r[3]) : "r"(addr));
}

__device__ __forceinline__ void ldsm4t(uint32_t* r, uint32_t addr) {
    asm volatile("ldmatrix.sync.aligned.m8n8.x4.trans.shared.b16 {%0,%1,%2,%3}, [%4];"
        : "=r"(r[0]), "=r"(r[1]), "=r"(r[2]), "=r"(r[3]) : "r"(addr));
}

__device__ __forceinline__ void mma16816(float* c, const uint32_t* a, const uint32_t* b) {
    asm volatile("mma.sync.aligned.m16n8k16.row.col.f32.f16.f16.f32 "
        "{%0,%1,%2,%3}, {%4,%5,%6,%7}, {%8,%9}, {%0,%1,%2,%3};"
        : "+f"(c[0]), "+f"(c[1]), "+f"(c[2]), "+f"(c[3])
        : "r"(a[0]), "r"(a[1]), "r"(a[2]), "r"(a[3]), "r"(b[0]), "r"(b[1]));
}

#define CP_ASYNC16(so, ga) \
    asm volatile("cp.async.cg.shared.global [%0], [%1], 16;\n" :: "r"(so), "l"(ga))
#define CP_COMMIT() asm volatile("cp.async.commit_group;\n" ::: "memory")
#define CP_WAIT(n)  asm volatile("cp.async.wait_group %0;\n" :: "n"(n) : "memory")

// ---------------------------------------------------------------------------
// cvt3: q/k/v fp32 -> fp16, one launch (vectorized 16B store)
// ---------------------------------------------------------------------------
__global__ void cvt3_kernel(const float* __restrict__ x0,
                            const float* __restrict__ x1,
                            const float* __restrict__ x2)
{
    const int z = blockIdx.y;
    const float* x = (z == 0) ? x0 : (z == 1) ? x1 : x2;
    __half* dst = g_inH3 + (size_t)z * (MTOK * EMBED);
    const int i = blockIdx.x * 256 + threadIdx.x;
    const float4* xp = reinterpret_cast<const float4*>(x) + 2 * (size_t)i;
    float4 a = xp[0], b = xp[1];
    __half2 h0 = __floats2half2_rn(a.x, a.y);
    __half2 h1 = __floats2half2_rn(a.z, a.w);
    __half2 h2 = __floats2half2_rn(b.x, b.y);
    __half2 h3 = __floats2half2_rn(b.z, b.w);
    uint4 o;
    o.x = *reinterpret_cast<uint32_t*>(&h0);
    o.y = *reinterpret_cast<uint32_t*>(&h1);
    o.z = *reinterpret_cast<uint32_t*>(&h2);
    o.w = *reinterpret_cast<uint32_t*>(&h3);
    reinterpret_cast<uint4*>(dst)[i] = o;
}

// ---------------------------------------------------------------------------
// wcvt: all 7 weights fp32 -> fp16 in one launch
// ---------------------------------------------------------------------------
#define WSEG4 (RANK * EMBED / 4)
__global__ void wcvt_kernel(const float* __restrict__ p0, const float* __restrict__ p1,
                            const float* __restrict__ p2, const float* __restrict__ p3,
                            const float* __restrict__ p4, const float* __restrict__ p5,
                            const float* __restrict__ p6)
{
    const int i = blockIdx.x * 256 + threadIdx.x;
    int seg, off;
    if (i >= 6 * WSEG4) { seg = 6; off = i - 6 * WSEG4; }
    else                { seg = i / WSEG4; off = i % WSEG4; }
    const float* ps[7] = {p0, p1, p2, p3, p4, p5, p6};
    float4 v = reinterpret_cast<const float4*>(ps[seg])[off];
    __half2* yp = reinterpret_cast<__half2*>(g_wH) + 2 * (size_t)i;
    yp[0] = __floats2half2_rn(v.x, v.y);
    yp[1] = __floats2half2_rn(v.z, v.w);
}

// ---------------------------------------------------------------------------
// fused mma.sync fp16 NT GEMM. Tile 128x128, BK=64, 8 warps, 3-stage, 2 CTA/SM.
// KIND 0: down3. KIND 1: up3 (bias, elu for z<2; z==1 also accumulates ksum).
// KIND 2: Wo (fp32 + bias)
// ---------------------------------------------------------------------------
#define BKC        64
#define RSTRIDE_B  144
#define A_TILE_BY  (128 * RSTRIDE_B)
#define B_TILE_BY  (128 * RSTRIDE_B)
#define STAGE_BY   (A_TILE_BY + B_TILE_BY)
#define NSTAGE     3
#define SMEM_GEMM  (NSTAGE * STAGE_BY)      // 110592
#define OFF_A      0
#define OFF_B      A_TILE_BY

__device__ __forceinline__ void load_stage_mma(
    uint32_t sb, int tid, int s, int k0,
    const __half* __restrict__ A, const __half* __restrict__ B,
    int K, int aRow0, int bRow0)
{
    const uint32_t stage = sb + (uint32_t)s * STAGE_BY;
#pragma unroll
    for (int i = 0; i < 8; ++i) {
        int idx = tid + i * 256;
        int row = (idx & 1023) >> 3;
        int cb  = idx & 7;
        const __half* gp;
        int r0;
        uint32_t tbase;
        if (idx < 1024) { gp = A; r0 = aRow0; tbase = OFF_A; }
        else            { gp = B; r0 = bRow0; tbase = OFF_B; }
        const void* ga = gp + (size_t)(r0 + row) * K + k0 + cb * 8;
        uint32_t so = stage + tbase + (uint32_t)row * RSTRIDE_B + cb * 16;
        CP_ASYNC16(so, ga);
    }
    CP_COMMIT();
}

template <int KIND>
__global__ __launch_bounds__(256, 2) void gemm_fused(
    const float* __restrict__ b0, const float* __restrict__ b1,
    const float* __restrict__ b2, float* __restrict__ outF)
{
    constexpr int NN = (KIND == 0) ? RANK : EMBED;
    constexpr int KK = (KIND == 0) ? EMBED : ((KIND == 1) ? RANK : EMBED);

    extern __shared__ char smem[];
    __shared__ float ksred[128];
    const uint32_t sb = smem_u32(smem);
    const int tid = threadIdx.x;
    const int wid = tid >> 5;
    const int lane = tid & 31;
    const int bn = blockIdx.x, bm = blockIdx.y;
    const int z = (KIND == 2) ? 0 : blockIdx.z;
    const int warp_m = wid >> 2;
    const int warp_n = wid & 3;
    const int aRow0 = bm * 128, bRow0 = bn * 128;

    const __half* A;
    const __half* B;
    __half* Ch = nullptr;
    const float* bias = nullptr;
    bool elu = false;
    if (KIND == 0) {
        A = g_inH3 + (size_t)z * (MTOK * EMBED);
        B = g_wH + (size_t)z * (2 * RANK * EMBED);
        Ch = g_yH3 + (size_t)z * (MTOK * RANK);
    } else if (KIND == 1) {
        A = g_yH3 + (size_t)z * (MTOK * RANK);
        B = g_wH + W_QU + (size_t)z * (2 * RANK * EMBED);
        bias = (z == 0) ? b0 : (z == 1) ? b1 : b2;
        Ch = (z == 0) ? g_QH : (z == 1) ? g_KH : g_VH;
        elu = (z < 2);
    } else {
        A = g_atH;
        B = g_wH + W_O;
        bias = b0;
    }

    float acc[4][4][4];
#pragma unroll
    for (int mt = 0; mt < 4; ++mt)
#pragma unroll
        for (int nt = 0; nt < 4; ++nt)
#pragma unroll
            for (int j = 0; j < 4; ++j) acc[mt][nt][j] = 0.f;

    const int nch = KK / BKC;

    load_stage_mma(sb, tid, 0, 0,   A, B, KK, aRow0, bRow0);
    load_stage_mma(sb, tid, 1, BKC, A, B, KK, aRow0, bRow0);

    const int a_r = lane & 15;
    const int a_c = (lane >> 4) * 8;
    const int b_n = ((lane >> 4) << 3) + (lane & 7);
    const int b_k = ((lane >> 3) & 1) * 8;

    for (int c = 0; c < nch; ++c) {
        if (c == nch - 1) { CP_WAIT(0); } else { CP_WAIT(1); }
        __syncthreads();

        if (c + 2 < nch)
            load_stage_mma(sb, tid, (c + 2) % NSTAGE, (c + 2) * BKC,
                           A, B, KK, aRow0, bRow0);

        const uint32_t st = sb + (uint32_t)(c % NSTAGE) * STAGE_BY;
#pragma unroll
        for (int ks = 0; ks < 4; ++ks) {
            const int k0 = ks * 16;
            uint32_t ar[4][4];
#pragma unroll
            for (int mt = 0; mt < 4; ++mt) {
                uint32_t off = (uint32_t)(warp_m * 64 + mt * 16 + a_r) * RSTRIDE_B
                             + (uint32_t)(k0 + a_c) * 2;
                ldsm4(ar[mt], st + OFF_A + off);
            }
            uint32_t br[4][2];
#pragma unroll
            for (int nt2 = 0; nt2 < 2; ++nt2) {
                uint32_t off = (uint32_t)(warp_n * 32 + nt2 * 16 + b_n) * RSTRIDE_B
                             + (uint32_t)(k0 + b_k) * 2;
                uint32_t t4[4];
                ldsm4(t4, st + OFF_B + off);
                br[nt2*2][0] = t4[0]; br[nt2*2][1] = t4[1];
                br[nt2*2+1][0] = t4[2]; br[nt2*2+1][1] = t4[3];
            }
#pragma unroll
            for (int mt = 0; mt < 4; ++mt)
#pragma unroll
                for (int nt = 0; nt < 4; ++nt)
                    mma16816(acc[mt][nt], ar[mt], br[nt]);
        }
    }

    // epilogue (+ fused ksum partials for KIND 1, z == 1)
    const bool do_ks = (KIND == 1) && (z == 1);
    if (do_ks) {
        if (tid < 128) ksred[tid] = 0.f;
        __syncthreads();
    }
    float ksp[4][2];
#pragma unroll
    for (int nt = 0; nt < 4; ++nt) { ksp[nt][0] = 0.f; ksp[nt][1] = 0.f; }

#pragma unroll
    for (int mt = 0; mt < 4; ++mt) {
#pragma unroll
        for (int nt = 0; nt < 4; ++nt) {
            const int row0 = bm * 128 + warp_m * 64 + mt * 16 + (lane >> 2);
            const int col  = bn * 128 + warp_n * 32 + nt * 8 + (lane & 3) * 2;
#pragma unroll
            for (int h = 0; h < 2; ++h) {
                const int row = row0 + h * 8;
                float f0 = acc[mt][nt][h * 2 + 0];
                float f1 = acc[mt][nt][h * 2 + 1];
                if (KIND >= 1) {
                    f0 += __ldg(bias + col);
                    f1 += __ldg(bias + col + 1);
                }
                if (KIND == 1 && elu) {
                    f0 = (f0 > 0.f) ? (f0 + 1.f) : __expf(f0);
                    f1 = (f1 > 0.f) ? (f1 + 1.f) : __expf(f1);
                }
                if (do_ks) { ksp[nt][0] += f0; ksp[nt][1] += f1; }
                if (KIND == 2) {
                    *reinterpret_cast<float2*>(outF + (size_t)row * NN + col) =
                        make_float2(f0, f1);
                } else {
                    *reinterpret_cast<__half2*>(Ch + (size_t)row * NN + col) =
                        __floats2half2_rn(f0, f1);
                }
            }
        }
    }

    if (do_ks) {
        // reduce per-CTA column sums in smem, then 128 global atomics
#pragma unroll
        for (int nt = 0; nt < 4; ++nt) {
            const int cloc = warp_n * 32 + nt * 8 + (lane & 3) * 2;
            atomicAdd(&ksred[cloc],     ksp[nt][0]);
            atomicAdd(&ksred[cloc + 1], ksp[nt][1]);
        }
        __syncthreads();
        if (tid < 128) {
            const int gcol = bn * 128 + tid;
            const int bb = bm >> 6;                 // (bm*128)/8192
            const int bh = bb * 16 + (gcol >> 6);
            atomicAdd(g_kvks + KV_ELEMS + bh * 64 + (gcol & 63), ksred[tid]);
        }
    }
}

// ---------------------------------------------------------------------------
// zero kernel
// ---------------------------------------------------------------------------
__global__ void zero_kernel(float* __restrict__ p, int n)
{
    int i = blockIdx.x * blockDim.x + threadIdx.x;
    if (i < n) p[i] = 0.f;
}

// ---------------------------------------------------------------------------
// kv via MMA: kv[bh][d][e] += sum_n k[n,d]*v[n,e]
// ---------------------------------------------------------------------------
#define KVNCH   4
#define KVTOK   (Nseq / KVNCH)
#define KV_STR  144
#define KV_TILE (64 * KV_STR)
#define KV_STG  (2 * KV_TILE)

__global__ __launch_bounds__(256, 2) void kv_mma_kernel(
    const __half* __restrict__ KH, const __half* __restrict__ VH,
    float* __restrict__ kv)
{
    __shared__ char smem[3 * KV_STG];
    const uint32_t sb = smem_u32(smem);

    const int bh = blockIdx.x;
    const int b = bh >> 4, h = bh & 15;
    const int chunk = blockIdx.y;
    const int tid = threadIdx.x;
    const int wid = tid >> 5;
    const int lane = tid & 31;
    const int warp_m = wid >> 1;
    const int warp_n = wid & 1;

    const size_t tokBase = (size_t)b * Nseq + (size_t)chunk * KVTOK;

    const int atr = (lane & 7) + ((lane >> 4) << 3);
    const int atc = ((lane >> 3) & 1) * 16;
    const int btr = (lane & 7) + ((lane >> 3) & 1) * 8;
    const int btc = (lane >> 4) * 16;

    float acc[4][4];
#pragma unroll
    for (int nt = 0; nt < 4; ++nt)
#pragma unroll
        for (int j = 0; j < 4; ++j) acc[nt][j] = 0.f;

    const int niter = KVTOK / 64;

    auto load_tile = [&](int s, int it) {
        const uint32_t stage = sb + (uint32_t)s * KV_STG;
#pragma unroll
        for (int i = 0; i < 4; ++i) {
            int idx = tid + i * 256;
            int tile = idx >> 9;
            int w = idx & 511;
            int row = w >> 3, cb = w & 7;
            const __half* gp = tile ? VH : KH;
            const void* ga = gp + (tokBase + (size_t)it * 64 + row) * EMBED + h * HDIM + cb * 8;
            uint32_t so = stage + (uint32_t)tile * KV_TILE + (uint32_t)row * KV_STR + cb * 16;
            CP_ASYNC16(so, ga);
        }
        CP_COMMIT();
    };

    load_tile(0, 0);
    load_tile(1, 1);

    for (int it = 0; it < niter; ++it) {
        if (it == niter - 1) { CP_WAIT(0); } else { CP_WAIT(1); }
        __syncthreads();

        if (it + 2 < niter)
            load_tile((it + 2) % 3, it + 2);

        const uint32_t st = sb + (uint32_t)(it % 3) * KV_STG;
        const uint32_t kb = st;
        const uint32_t vb = st + KV_TILE;

#pragma unroll
        for (int ts = 0; ts < 4; ++ts) {
            const int t0 = ts * 16;
            uint32_t a4[4];
            ldsm4t(a4, kb + (uint32_t)(t0 + atr) * KV_STR
                      + (uint32_t)(warp_m * 32) + atc);
            uint32_t br[4][2];
#pragma unroll
            for (int nt2 = 0; nt2 < 2; ++nt2) {
                uint32_t t4[4];
                ldsm4t(t4, vb + (uint32_t)(t0 + btr) * KV_STR
                          + (uint32_t)(warp_n * 64 + nt2 * 32) + btc);
                br[nt2*2][0]   = t4[0]; br[nt2*2][1]   = t4[1];
                br[nt2*2+1][0] = t4[2]; br[nt2*2+1][1] = t4[3];
            }
#pragma unroll
            for (int nt = 0; nt < 4; ++nt)
                mma16816(acc[nt], a4, br[nt]);
        }
    }

    float* kvp = kv + (size_t)bh * (HDIM * HDIM);
#pragma unroll
    for (int nt = 0; nt < 4; ++nt) {
#pragma unroll
        for (int hh = 0; hh < 2; ++hh) {
            const int d = warp_m * 16 + (lane >> 2) + hh * 8;
            const int e = warp_n * 32 + nt * 8 + (lane & 3) * 2;
            atomicAdd(kvp + d * HDIM + e,     acc[nt][hh * 2 + 0]);
            atomicAdd(kvp + d * HDIM + e + 1, acc[nt][hh * 2 + 1]);
        }
    }
}

// ---------------------------------------------------------------------------
// kvT convert
// ---------------------------------------------------------------------------
__global__ __launch_bounds__(256) void kvT_cvt_kernel(
    const float* __restrict__ kv, __half* __restrict__ kvTh)
{
    const int bh = blockIdx.x;
    const int tid = threadIdx.x;
    __shared__ float s[64][65];
    for (int i = tid; i < 4096; i += 256)
        s[i >> 6][i & 63] = kv[(size_t)bh * 4096 + i];
    __syncthreads();
    for (int i = tid; i < 4096; i += 256) {
        const int e = i >> 6, d = i & 63;
        kvTh[(size_t)bh * 4096 + i] = __float2half(s[d][e]);
    }
}

// ---------------------------------------------------------------------------
// attn numerator via MMA + fused denominator
// ---------------------------------------------------------------------------
#define AT_STR 144
__global__ __launch_bounds__(256) void attn_mma_kernel(
    const __half* __restrict__ Qh, const __half* __restrict__ kvTh,
    const float* __restrict__ ksum, __half* __restrict__ atH)
{
    __shared__ char smem[128 * AT_STR + 64 * AT_STR];
    __shared__ float ks_s[64];
    __shared__ float dinv_s[128];
    const uint32_t sq = smem_u32(smem);
    const uint32_t skt = sq + 128 * AT_STR;

    const int bh = blockIdx.x;
    const int b = bh >> 4, h = bh & 15;
    const int tt = blockIdx.y;
    const int tid = threadIdx.x;
    const int wid = tid >> 5;
    const int lane = tid & 31;
    const int warp_m = wid >> 1;
    const int warp_n = wid & 1;

#pragma unroll
    for (int i = 0; i < 4; ++i) {
        int idx = tid + i * 256;
        int row = idx >> 3, cb = idx & 7;
        const void* ga = Qh + ((size_t)b * Nseq + tt * 128 + row) * EMBED + h * HDIM + cb * 8;
        CP_ASYNC16(sq + (uint32_t)row * AT_STR + cb * 16, ga);
    }
#pragma unroll
    for (int i = 0; i < 2; ++i) {
        int idx = tid + i * 256;
        int row = idx >> 3, cb = idx & 7;
        const void* ga = kvTh + (size_t)bh * 4096 + row * 64 + cb * 8;
        CP_ASYNC16(skt + (uint32_t)row * AT_STR + cb * 16, ga);
    }
    if (tid < 64) ks_s[tid] = ksum[bh * 64 + tid];
    CP_COMMIT();
    CP_WAIT(0);
    __syncthreads();

    if (tid < 128) {
        const uint32_t qrow = sq + (uint32_t)tid * AT_STR;
        float d = 0.f;
#pragma unroll
        for (int j = 0; j < 32; ++j) {
            uint32_t packed;
            asm volatile("ld.shared.b32 %0, [%1];" : "=r"(packed) : "r"(qrow + j * 4));
            __half2 q2 = *reinterpret_cast<__half2*>(&packed);
            float2 qf = __half22float2(q2);
            d = fmaf(qf.x, ks_s[2 * j], d);
            d = fmaf(qf.y, ks_s[2 * j + 1], d);
        }
        dinv_s[tid] = 1.0f / (d + 1e-6f);
    }
    __syncthreads();

    const int a_r = lane & 15;
    const int a_c = (lane >> 4) * 8;
    const int b_n = ((lane >> 4) << 3) + (lane & 7);
    const int b_k = ((lane >> 3) & 1) * 8;

    float acc[2][4][4];
#pragma unroll
    for (int mt = 0; mt < 2; ++mt)
#pragma unroll
        for (int nt = 0; nt < 4; ++nt)
#pragma unroll
            for (int j = 0; j < 4; ++j) acc[mt][nt][j] = 0.f;

#pragma unroll
    for (int ks = 0; ks < 4; ++ks) {
        const int k0 = ks * 16;
        uint32_t ar[2][4];
#pragma unroll
        for (int mt = 0; mt < 2; ++mt) {
            uint32_t off = (uint32_t)(warp_m * 32 + mt * 16 + a_r) * AT_STR
                         + (uint32_t)(k0 + a_c) * 2;
            ldsm4(ar[mt], sq + off);
        }
        uint32_t br[4][2];
#pragma unroll
        for (int nt2 = 0; nt2 < 2; ++nt2) {
            uint32_t off = (uint32_t)(warp_n * 32 + nt2 * 16 + b_n) * AT_STR
                         + (uint32_t)(k0 + b_k) * 2;
            uint32_t t4[4];
            ldsm4(t4, skt + off);
            br[nt2*2][0] = t4[0]; br[nt2*2][1] = t4[1];
            br[nt2*2+1][0] = t4[2]; br[nt2*2+1][1] = t4[3];
        }
#pragma unroll
        for (int mt = 0; mt < 2; ++mt)
#pragma unroll
            for (int nt = 0; nt < 4; ++nt)
                mma16816(acc[mt][nt], ar[mt], br[nt]);
    }

#pragma unroll
    for (int mt = 0; mt < 2; ++mt) {
#pragma unroll
        for (int hh = 0; hh < 2; ++hh) {
            const int rloc = warp_m * 32 + mt * 16 + (lane >> 2) + hh * 8;
            const float dv = dinv_s[rloc];
            const size_t ob = ((size_t)b * Nseq + tt * 128 + rloc) * EMBED + h * HDIM;
#pragma unroll
            for (int nt = 0; nt < 4; ++nt) {
                const int col = warp_n * 32 + nt * 8 + (lane & 3) * 2;
                float f0 = acc[mt][nt][hh * 2 + 0] * dv;
                float f1 = acc[mt][nt][hh * 2 + 1] * dv;
                *reinterpret_cast<__half2*>(atH + ob + col) = __floats2half2_rn(f0, f1);
            }
        }
    }
}

// ---------------------------------------------------------------------------
// launch
// ---------------------------------------------------------------------------
extern "C" void kernel_launch(void* const* d_in, const int* in_sizes, int n_in,
                              void* d_out, int out_size)
{
    const float* query   = (const float*)d_in[0];
    const float* key_    = (const float*)d_in[1];
    const float* value   = (const float*)d_in[2];
    const float* Wq_down = (const float*)d_in[3];
    const float* Wq_up   = (const float*)d_in[4];
    const float* bq_up   = (const float*)d_in[5];
    const float* Wk_down = (const float*)d_in[6];
    const float* Wk_up   = (const float*)d_in[7];
    const float* bk_up   = (const float*)d_in[8];
    const float* Wv_down = (const float*)d_in[9];
    const float* Wv_up   = (const float*)d_in[10];
    const float* bv_up   = (const float*)d_in[11];
    const float* Wo      = (const float*)d_in[12];
    const float* bo      = (const float*)d_in[13];
    float* out = (float*)d_out;

    __half *QH, *KH, *VH, *atH, *kvTh;
    float *KVKS;
    cudaGetSymbolAddress((void**)&QH,   g_QH);
    cudaGetSymbolAddress((void**)&KH,   g_KH);
    cudaGetSymbolAddress((void**)&VH,   g_VH);
    cudaGetSymbolAddress((void**)&atH,  g_atH);
    cudaGetSymbolAddress((void**)&kvTh, g_kvTh);
    cudaGetSymbolAddress((void**)&KVKS, g_kvks);
    float* KV = KVKS;
    float* KS = KVKS + KV_ELEMS;

    cudaFuncSetAttribute((const void*)gemm_fused<0>, cudaFuncAttributeMaxDynamicSharedMemorySize, SMEM_GEMM);
    cudaFuncSetAttribute((const void*)gemm_fused<1>, cudaFuncAttributeMaxDynamicSharedMemorySize, SMEM_GEMM);
    cudaFuncSetAttribute((const void*)gemm_fused<2>, cudaFuncAttributeMaxDynamicSharedMemorySize, SMEM_GEMM);

    const dim3 blk(256);

    // zero ksum/kv accumulators first (independent of GEMM inputs)
    const int nz = KV_ELEMS + KS_ELEMS;
    zero_kernel<<<(nz + 255) / 256, blk>>>(KVKS, nz);

    // converts (2 launches)
    wcvt_kernel<<<(6 * WSEG4 + EMBED*EMBED/4 + 255) / 256, blk>>>(
        Wq_down, Wq_up, Wk_down, Wk_up, Wv_down, Wv_up, Wo);
    cvt3_kernel<<<dim3(MTOK * EMBED / 8 / 256, 3), blk>>>(query, key_, value);

    // down projections (one launch, z = q/k/v)
    gemm_fused<0><<<dim3(RANK / 128, MTOK / 128, 3), blk, SMEM_GEMM>>>(
        nullptr, nullptr, nullptr, nullptr);
    // up projections (one launch, z = q/k/v; elu for q,k; ksum fused for z==1)
    gemm_fused<1><<<dim3(EMBED / 128, MTOK / 128, 3), blk, SMEM_GEMM>>>(
        bq_up, bk_up, bv_up, nullptr);

    // kv (MMA)
    kv_mma_kernel<<<dim3(BH, KVNCH), blk>>>(KH, VH, KV);
    kvT_cvt_kernel<<<BH, blk>>>(KV, kvTh);

    // attention numerator (MMA) + fused denom + divide
    attn_mma_kernel<<<dim3(BH, Nseq / 128), blk>>>(QH, kvTh, KS, atH);

    // output projection (fp32 out)
    gemm_fused<2><<<dim3(EMBED / 128, MTOK / 128, 1), blk, SMEM_GEMM>>>(
        bo, nullptr, nullptr, out);
}

// round 15
// speedup vs baseline: 1.1509x; 1.0001x over previous
#include <cuda_runtime.h>
#include <cuda_fp16.h>
#include <cstdint>

// ---------------------------------------------------------------------------
// Problem constants
// ---------------------------------------------------------------------------
#define Bv     4
#define Nseq   8192
#define EMBED  1024
#define HEADS  16
#define HDIM   64
#define RANK   512
#define MTOK   (Bv * Nseq)          // 32768
#define BH     (Bv * HEADS)         // 64

// ---------------------------------------------------------------------------
// Scratch (__device__ globals; allocation forbidden)
// ---------------------------------------------------------------------------
__device__ __half g_inH3[(size_t)3 * MTOK * EMBED];
__device__ __half g_yH3 [(size_t)3 * MTOK * RANK];
__device__ __half g_QH [MTOK * EMBED];
__device__ __half g_KH [MTOK * EMBED];
__device__ __half g_VH [MTOK * EMBED];
__device__ __half g_atH[MTOK * EMBED];

#define W_QD 0
#define W_QU (W_QD + RANK*EMBED)
#define W_KD (W_QU + EMBED*RANK)
#define W_KU (W_KD + RANK*EMBED)
#define W_VD (W_KU + EMBED*RANK)
#define W_VU (W_VD + RANK*EMBED)
#define W_O  (W_VU + EMBED*RANK)
#define W_TOT (W_O + EMBED*EMBED)
__device__ __half g_wH[W_TOT];

#define KV_ELEMS (BH * HDIM * HDIM)
#define KS_ELEMS (BH * HDIM)
__device__ float  g_kvks[KV_ELEMS + KS_ELEMS];
__device__ __half g_kvTh[KV_ELEMS];

// ---------------------------------------------------------------------------
// helpers
// ---------------------------------------------------------------------------
__device__ __forceinline__ uint32_t smem_u32(const void* p) {
    uint32_t a;
    asm("{ .reg .u64 t; cvta.to.shared.u64 t, %1; cvt.u32.u64 %0, t; }"
        : "=r"(a) : "l"(p));
    return a;
}

__device__ __forceinline__ void ldsm4(uint32_t* r, uint32_t addr) {
    asm volatile("ldmatrix.sync.aligned.m8n8.x4.shared.b16 {%0,%1,%2,%3}, [%4];"
        : "=r"(r[0]), "=r"(r[1]), "=r"(r[2]), "=r"(r[3]) : "r"(addr));
}

__device__ __forceinline__ void ldsm4t(uint32_t* r, uint32_t addr) {
    asm volatile("ldmatrix.sync.aligned.m8n8.x4.trans.shared.b16 {%0,%1,%2,%3}, [%4];"
        : "=r"(r[0]), "=r"(r[1]), "=r"(r[2]), "=r"(r[3]) : "r"(addr));
}

__device__ __forceinline__ void mma16816(float* c, const uint32_t* a, const uint32_t* b) {
    asm volatile("mma.sync.aligned.m16n8k16.row.col.f32.f16.f16.f32 "
        "{%0,%1,%2,%3}, {%4,%5,%6,%7}, {%8,%9}, {%0,%1,%2,%3};"
        : "+f"(c[0]), "+f"(c[1]), "+f"(c[2]), "+f"(c[3])
        : "r"(a[0]), "r"(a[1]), "r"(a[2]), "r"(a[3]), "r"(b[0]), "r"(b[1]));
}

#define CP_ASYNC16(so, ga) \
    asm volatile("cp.async.cg.shared.global [%0], [%1], 16;\n" :: "r"(so), "l"(ga))
#define CP_COMMIT() asm volatile("cp.async.commit_group;\n" ::: "memory")
#define CP_WAIT(n)  asm volatile("cp.async.wait_group %0;\n" :: "n"(n) : "memory")

// ---------------------------------------------------------------------------
// cvt3: q/k/v fp32 -> fp16, one launch (vectorized 16B store)
// ---------------------------------------------------------------------------
__global__ void cvt3_kernel(const float* __restrict__ x0,
                            const float* __restrict__ x1,
                            const float* __restrict__ x2)
{
    const int z = blockIdx.y;
    const float* x = (z == 0) ? x0 : (z == 1) ? x1 : x2;
    __half* dst = g_inH3 + (size_t)z * (MTOK * EMBED);
    const int i = blockIdx.x * 256 + threadIdx.x;
    const float4* xp = reinterpret_cast<const float4*>(x) + 2 * (size_t)i;
    float4 a = xp[0], b = xp[1];
    __half2 h0 = __floats2half2_rn(a.x, a.y);
    __half2 h1 = __floats2half2_rn(a.z, a.w);
    __half2 h2 = __floats2half2_rn(b.x, b.y);
    __half2 h3 = __floats2half2_rn(b.z, b.w);
    uint4 o;
    o.x = *reinterpret_cast<uint32_t*>(&h0);
    o.y = *reinterpret_cast<uint32_t*>(&h1);
    o.z = *reinterpret_cast<uint32_t*>(&h2);
    o.w = *reinterpret_cast<uint32_t*>(&h3);
    reinterpret_cast<uint4*>(dst)[i] = o;
}

// ---------------------------------------------------------------------------
// wcvt: all 7 weights fp32 -> fp16 in one launch
// ---------------------------------------------------------------------------
#define WSEG4 (RANK * EMBED / 4)
__global__ void wcvt_kernel(const float* __restrict__ p0, const float* __restrict__ p1,
                            const float* __restrict__ p2, const float* __restrict__ p3,
                            const float* __restrict__ p4, const float* __restrict__ p5,
                            const float* __restrict__ p6)
{
    const int i = blockIdx.x * 256 + threadIdx.x;
    int seg, off;
    if (i >= 6 * WSEG4) { seg = 6; off = i - 6 * WSEG4; }
    else                { seg = i / WSEG4; off = i % WSEG4; }
    const float* ps[7] = {p0, p1, p2, p3, p4, p5, p6};
    float4 v = reinterpret_cast<const float4*>(ps[seg])[off];
    __half2* yp = reinterpret_cast<__half2*>(g_wH) + 2 * (size_t)i;
    yp[0] = __floats2half2_rn(v.x, v.y);
    yp[1] = __floats2half2_rn(v.z, v.w);
}

// ---------------------------------------------------------------------------
// fused mma.sync fp16 NT GEMM. Tile 128x128, BK=64, 8 warps, 3-stage, 2 CTA/SM.
// KIND 0: down3. KIND 1: up3 (bias, elu for z<2; z==1 also accumulates ksum).
// KIND 2: Wo (fp32 + bias)
// ---------------------------------------------------------------------------
#define BKC        64
#define RSTRIDE_B  144
#define A_TILE_BY  (128 * RSTRIDE_B)
#define B_TILE_BY  (128 * RSTRIDE_B)
#define STAGE_BY   (A_TILE_BY + B_TILE_BY)
#define NSTAGE     3
#define SMEM_GEMM  (NSTAGE * STAGE_BY)      // 110592
#define OFF_A      0
#define OFF_B      A_TILE_BY

__device__ __forceinline__ void load_stage_mma(
    uint32_t sb, int tid, int s, int k0,
    const __half* __restrict__ A, const __half* __restrict__ B,
    int K, int aRow0, int bRow0)
{
    const uint32_t stage = sb + (uint32_t)s * STAGE_BY;
#pragma unroll
    for (int i = 0; i < 8; ++i) {
        int idx = tid + i * 256;
        int row = (idx & 1023) >> 3;
        int cb  = idx & 7;
        const __half* gp;
        int r0;
        uint32_t tbase;
        if (idx < 1024) { gp = A; r0 = aRow0; tbase = OFF_A; }
        else            { gp = B; r0 = bRow0; tbase = OFF_B; }
        const void* ga = gp + (size_t)(r0 + row) * K + k0 + cb * 8;
        uint32_t so = stage + tbase + (uint32_t)row * RSTRIDE_B + cb * 16;
        CP_ASYNC16(so, ga);
    }
    CP_COMMIT();
}

template <int KIND>
__global__ __launch_bounds__(256, 2) void gemm_fused(
    const float* __restrict__ b0, const float* __restrict__ b1,
    const float* __restrict__ b2, float* __restrict__ outF)
{
    constexpr int NN = (KIND == 0) ? RANK : EMBED;
    constexpr int KK = (KIND == 0) ? EMBED : ((KIND == 1) ? RANK : EMBED);

    extern __shared__ char smem[];
    __shared__ float ksred[128];
    const uint32_t sb = smem_u32(smem);
    const int tid = threadIdx.x;
    const int wid = tid >> 5;
    const int lane = tid & 31;
    const int bn = blockIdx.x, bm = blockIdx.y;
    const int z = (KIND == 2) ? 0 : blockIdx.z;
    const int warp_m = wid >> 2;
    const int warp_n = wid & 3;
    const int aRow0 = bm * 128, bRow0 = bn * 128;

    const __half* A;
    const __half* B;
    __half* Ch = nullptr;
    const float* bias = nullptr;
    bool elu = false;
    if (KIND == 0) {
        A = g_inH3 + (size_t)z * (MTOK * EMBED);
        B = g_wH + (size_t)z * (2 * RANK * EMBED);
        Ch = g_yH3 + (size_t)z * (MTOK * RANK);
    } else if (KIND == 1) {
        A = g_yH3 + (size_t)z * (MTOK * RANK);
        B = g_wH + W_QU + (size_t)z * (2 * RANK * EMBED);
        bias = (z == 0) ? b0 : (z == 1) ? b1 : b2;
        Ch = (z == 0) ? g_QH : (z == 1) ? g_KH : g_VH;
        elu = (z < 2);
    } else {
        A = g_atH;
        B = g_wH + W_O;
        bias = b0;
    }

    float acc[4][4][4];
#pragma unroll
    for (int mt = 0; mt < 4; ++mt)
#pragma unroll
        for (int nt = 0; nt < 4; ++nt)
#pragma unroll
            for (int j = 0; j < 4; ++j) acc[mt][nt][j] = 0.f;

    const int nch = KK / BKC;

    load_stage_mma(sb, tid, 0, 0,   A, B, KK, aRow0, bRow0);
    load_stage_mma(sb, tid, 1, BKC, A, B, KK, aRow0, bRow0);

    const int a_r = lane & 15;
    const int a_c = (lane >> 4) * 8;
    const int b_n = ((lane >> 4) << 3) + (lane & 7);
    const int b_k = ((lane >> 3) & 1) * 8;

    for (int c = 0; c < nch; ++c) {
        if (c == nch - 1) { CP_WAIT(0); } else { CP_WAIT(1); }
        __syncthreads();

        if (c + 2 < nch)
            load_stage_mma(sb, tid, (c + 2) % NSTAGE, (c + 2) * BKC,
                           A, B, KK, aRow0, bRow0);

        const uint32_t st = sb + (uint32_t)(c % NSTAGE) * STAGE_BY;
#pragma unroll
        for (int ks = 0; ks < 4; ++ks) {
            const int k0 = ks * 16;
            uint32_t ar[4][4];
#pragma unroll
            for (int mt = 0; mt < 4; ++mt) {
                uint32_t off = (uint32_t)(warp_m * 64 + mt * 16 + a_r) * RSTRIDE_B
                             + (uint32_t)(k0 + a_c) * 2;
                ldsm4(ar[mt], st + OFF_A + off);
            }
            uint32_t br[4][2];
#pragma unroll
            for (int nt2 = 0; nt2 < 2; ++nt2) {
                uint32_t off = (uint32_t)(warp_n * 32 + nt2 * 16 + b_n) * RSTRIDE_B
                             + (uint32_t)(k0 + b_k) * 2;
                uint32_t t4[4];
                ldsm4(t4, st + OFF_B + off);
                br[nt2*2][0] = t4[0]; br[nt2*2][1] = t4[1];
                br[nt2*2+1][0] = t4[2]; br[nt2*2+1][1] = t4[3];
            }
#pragma unroll
            for (int mt = 0; mt < 4; ++mt)
#pragma unroll
                for (int nt = 0; nt < 4; ++nt)
                    mma16816(acc[mt][nt], ar[mt], br[nt]);
        }
    }

    // epilogue (+ fused ksum partials for KIND 1, z == 1)
    const bool do_ks = (KIND == 1) && (z == 1);
    if (do_ks) {
        if (tid < 128) ksred[tid] = 0.f;
        __syncthreads();
    }
    float ksp[4][2];
#pragma unroll
    for (int nt = 0; nt < 4; ++nt) { ksp[nt][0] = 0.f; ksp[nt][1] = 0.f; }

#pragma unroll
    for (int mt = 0; mt < 4; ++mt) {
#pragma unroll
        for (int nt = 0; nt < 4; ++nt) {
            const int row0 = bm * 128 + warp_m * 64 + mt * 16 + (lane >> 2);
            const int col  = bn * 128 + warp_n * 32 + nt * 8 + (lane & 3) * 2;
#pragma unroll
            for (int h = 0; h < 2; ++h) {
                const int row = row0 + h * 8;
                float f0 = acc[mt][nt][h * 2 + 0];
                float f1 = acc[mt][nt][h * 2 + 1];
                if (KIND >= 1) {
                    f0 += __ldg(bias + col);
                    f1 += __ldg(bias + col + 1);
                }
                if (KIND == 1 && elu) {
                    f0 = (f0 > 0.f) ? (f0 + 1.f) : __expf(f0);
                    f1 = (f1 > 0.f) ? (f1 + 1.f) : __expf(f1);
                }
                if (do_ks) { ksp[nt][0] += f0; ksp[nt][1] += f1; }
                if (KIND == 2) {
                    *reinterpret_cast<float2*>(outF + (size_t)row * NN + col) =
                        make_float2(f0, f1);
                } else {
                    *reinterpret_cast<__half2*>(Ch + (size_t)row * NN + col) =
                        __floats2half2_rn(f0, f1);
                }
            }
        }
    }

    if (do_ks) {
#pragma unroll
        for (int nt = 0; nt < 4; ++nt) {
            const int cloc = warp_n * 32 + nt * 8 + (lane & 3) * 2;
            atomicAdd(&ksred[cloc],     ksp[nt][0]);
            atomicAdd(&ksred[cloc + 1], ksp[nt][1]);
        }
        __syncthreads();
        if (tid < 128) {
            const int gcol = bn * 128 + tid;
            const int bb = bm >> 6;
            const int bh = bb * 16 + (gcol >> 6);
            atomicAdd(g_kvks + KV_ELEMS + bh * 64 + (gcol & 63), ksred[tid]);
        }
    }
}

// ---------------------------------------------------------------------------
// zero kernel
// ---------------------------------------------------------------------------
__global__ void zero_kernel(float* __restrict__ p, int n)
{
    int i = blockIdx.x * blockDim.x + threadIdx.x;
    if (i < n) p[i] = 0.f;
}

// ---------------------------------------------------------------------------
// kv via MMA: kv[bh][d][e] += sum_n k[n,d]*v[n,e]
// ---------------------------------------------------------------------------
#define KVNCH   4
#define KVTOK   (Nseq / KVNCH)
#define KV_STR  144
#define KV_TILE (64 * KV_STR)
#define KV_STG  (2 * KV_TILE)

__global__ __launch_bounds__(256, 2) void kv_mma_kernel(
    const __half* __restrict__ KH, const __half* __restrict__ VH,
    float* __restrict__ kv)
{
    __shared__ char smem[3 * KV_STG];
    const uint32_t sb = smem_u32(smem);

    const int bh = blockIdx.x;
    const int b = bh >> 4, h = bh & 15;
    const int chunk = blockIdx.y;
    const int tid = threadIdx.x;
    const int wid = tid >> 5;
    const int lane = tid & 31;
    const int warp_m = wid >> 1;
    const int warp_n = wid & 1;

    const size_t tokBase = (size_t)b * Nseq + (size_t)chunk * KVTOK;

    const int atr = (lane & 7) + ((lane >> 4) << 3);
    const int atc = ((lane >> 3) & 1) * 16;
    const int btr = (lane & 7) + ((lane >> 3) & 1) * 8;
    const int btc = (lane >> 4) * 16;

    float acc[4][4];
#pragma unroll
    for (int nt = 0; nt < 4; ++nt)
#pragma unroll
        for (int j = 0; j < 4; ++j) acc[nt][j] = 0.f;

    const int niter = KVTOK / 64;

    auto load_tile = [&](int s, int it) {
        const uint32_t stage = sb + (uint32_t)s * KV_STG;
#pragma unroll
        for (int i = 0; i < 4; ++i) {
            int idx = tid + i * 256;
            int tile = idx >> 9;
            int w = idx & 511;
            int row = w >> 3, cb = w & 7;
            const __half* gp = tile ? VH : KH;
            const void* ga = gp + (tokBase + (size_t)it * 64 + row) * EMBED + h * HDIM + cb * 8;
            uint32_t so = stage + (uint32_t)tile * KV_TILE + (uint32_t)row * KV_STR + cb * 16;
            CP_ASYNC16(so, ga);
        }
        CP_COMMIT();
    };

    load_tile(0, 0);
    load_tile(1, 1);

    for (int it = 0; it < niter; ++it) {
        if (it == niter - 1) { CP_WAIT(0); } else { CP_WAIT(1); }
        __syncthreads();

        if (it + 2 < niter)
            load_tile((it + 2) % 3, it + 2);

        const uint32_t st = sb + (uint32_t)(it % 3) * KV_STG;
        const uint32_t kb = st;
        const uint32_t vb = st + KV_TILE;

#pragma unroll
        for (int ts = 0; ts < 4; ++ts) {
            const int t0 = ts * 16;
            uint32_t a4[4];
            ldsm4t(a4, kb + (uint32_t)(t0 + atr) * KV_STR
                      + (uint32_t)(warp_m * 32) + atc);
            uint32_t br[4][2];
#pragma unroll
            for (int nt2 = 0; nt2 < 2; ++nt2) {
                uint32_t t4[4];
                ldsm4t(t4, vb + (uint32_t)(t0 + btr) * KV_STR
                          + (uint32_t)(warp_n * 64 + nt2 * 32) + btc);
                br[nt2*2][0]   = t4[0]; br[nt2*2][1]   = t4[1];
                br[nt2*2+1][0] = t4[2]; br[nt2*2+1][1] = t4[3];
            }
#pragma unroll
            for (int nt = 0; nt < 4; ++nt)
                mma16816(acc[nt], a4, br[nt]);
        }
    }

    float* kvp = kv + (size_t)bh * (HDIM * HDIM);
#pragma unroll
    for (int nt = 0; nt < 4; ++nt) {
#pragma unroll
        for (int hh = 0; hh < 2; ++hh) {
            const int d = warp_m * 16 + (lane >> 2) + hh * 8;
            const int e = warp_n * 32 + nt * 8 + (lane & 3) * 2;
            atomicAdd(kvp + d * HDIM + e,     acc[nt][hh * 2 + 0]);
            atomicAdd(kvp + d * HDIM + e + 1, acc[nt][hh * 2 + 1]);
        }
    }
}

// ---------------------------------------------------------------------------
// kvT convert
// ---------------------------------------------------------------------------
__global__ __launch_bounds__(256) void kvT_cvt_kernel(
    const float* __restrict__ kv, __half* __restrict__ kvTh)
{
    const int bh = blockIdx.x;
    const int tid = threadIdx.x;
    __shared__ float s[64][65];
    for (int i = tid; i < 4096; i += 256)
        s[i >> 6][i & 63] = kv[(size_t)bh * 4096 + i];
    __syncthreads();
    for (int i = tid; i < 4096; i += 256) {
        const int e = i >> 6, d = i & 63;
        kvTh[(size_t)bh * 4096 + i] = __float2half(s[d][e]);
    }
}

// ---------------------------------------------------------------------------
// attn numerator via MMA + fused denominator; 2 token tiles per CTA
// ---------------------------------------------------------------------------
#define AT_STR 144
__global__ __launch_bounds__(256) void attn_mma_kernel(
    const __half* __restrict__ Qh, const __half* __restrict__ kvTh,
    const float* __restrict__ ksum, __half* __restrict__ atH)
{
    __shared__ char smem[2 * 128 * AT_STR + 64 * AT_STR];
    __shared__ float ks_s[64];
    __shared__ float dinv_s[128];
    const uint32_t sq0 = smem_u32(smem);
    const uint32_t sq1 = sq0 + 128 * AT_STR;
    const uint32_t skt = sq0 + 2 * 128 * AT_STR;

    const int bh = blockIdx.x;
    const int b = bh >> 4, h = bh & 15;
    const int tt0 = blockIdx.y * 2;        // two 128-token tiles
    const int tid = threadIdx.x;
    const int wid = tid >> 5;
    const int lane = tid & 31;
    const int warp_m = wid >> 1;
    const int warp_n = wid & 1;

    // group 1: Q0 + kvT
#pragma unroll
    for (int i = 0; i < 4; ++i) {
        int idx = tid + i * 256;
        int row = idx >> 3, cb = idx & 7;
        const void* ga = Qh + ((size_t)b * Nseq + tt0 * 128 + row) * EMBED + h * HDIM + cb * 8;
        CP_ASYNC16(sq0 + (uint32_t)row * AT_STR + cb * 16, ga);
    }
#pragma unroll
    for (int i = 0; i < 2; ++i) {
        int idx = tid + i * 256;
        int row = idx >> 3, cb = idx & 7;
        const void* ga = kvTh + (size_t)bh * 4096 + row * 64 + cb * 8;
        CP_ASYNC16(skt + (uint32_t)row * AT_STR + cb * 16, ga);
    }
    CP_COMMIT();
    // group 2: Q1
#pragma unroll
    for (int i = 0; i < 4; ++i) {
        int idx = tid + i * 256;
        int row = idx >> 3, cb = idx & 7;
        const void* ga = Qh + ((size_t)b * Nseq + (tt0 + 1) * 128 + row) * EMBED + h * HDIM + cb * 8;
        CP_ASYNC16(sq1 + (uint32_t)row * AT_STR + cb * 16, ga);
    }
    CP_COMMIT();

    if (tid < 64) ks_s[tid] = ksum[bh * 64 + tid];

    const int a_r = lane & 15;
    const int a_c = (lane >> 4) * 8;
    const int b_n = ((lane >> 4) << 3) + (lane & 7);
    const int b_k = ((lane >> 3) & 1) * 8;

#pragma unroll
    for (int t2 = 0; t2 < 2; ++t2) {
        const uint32_t sq = (t2 == 0) ? sq0 : sq1;
        if (t2 == 0) { CP_WAIT(1); } else { CP_WAIT(0); }
        __syncthreads();

        // fused denominator
        if (tid < 128) {
            const uint32_t qrow = sq + (uint32_t)tid * AT_STR;
            float d = 0.f;
#pragma unroll
            for (int j = 0; j < 32; ++j) {
                uint32_t packed;
                asm volatile("ld.shared.b32 %0, [%1];" : "=r"(packed) : "r"(qrow + j * 4));
                __half2 q2 = *reinterpret_cast<__half2*>(&packed);
                float2 qf = __half22float2(q2);
                d = fmaf(qf.x, ks_s[2 * j], d);
                d = fmaf(qf.y, ks_s[2 * j + 1], d);
            }
            dinv_s[tid] = 1.0f / (d + 1e-6f);
        }
        __syncthreads();

        float acc[2][4][4];
#pragma unroll
        for (int mt = 0; mt < 2; ++mt)
#pragma unroll
            for (int nt = 0; nt < 4; ++nt)
#pragma unroll
                for (int j = 0; j < 4; ++j) acc[mt][nt][j] = 0.f;

#pragma unroll
        for (int ks = 0; ks < 4; ++ks) {
            const int k0 = ks * 16;
            uint32_t ar[2][4];
#pragma unroll
            for (int mt = 0; mt < 2; ++mt) {
                uint32_t off = (uint32_t)(warp_m * 32 + mt * 16 + a_r) * AT_STR
                             + (uint32_t)(k0 + a_c) * 2;
                ldsm4(ar[mt], sq + off);
            }
            uint32_t br[4][2];
#pragma unroll
            for (int nt2 = 0; nt2 < 2; ++nt2) {
                uint32_t off = (uint32_t)(warp_n * 32 + nt2 * 16 + b_n) * AT_STR
                             + (uint32_t)(k0 + b_k) * 2;
                uint32_t t4[4];
                ldsm4(t4, skt + off);
                br[nt2*2][0] = t4[0]; br[nt2*2][1] = t4[1];
                br[nt2*2+1][0] = t4[2]; br[nt2*2+1][1] = t4[3];
            }
#pragma unroll
            for (int mt = 0; mt < 2; ++mt)
#pragma unroll
                for (int nt = 0; nt < 4; ++nt)
                    mma16816(acc[mt][nt], ar[mt], br[nt]);
        }

#pragma unroll
        for (int mt = 0; mt < 2; ++mt) {
#pragma unroll
            for (int hh = 0; hh < 2; ++hh) {
                const int rloc = warp_m * 32 + mt * 16 + (lane >> 2) + hh * 8;
                const float dv = dinv_s[rloc];
                const size_t ob = ((size_t)b * Nseq + (tt0 + t2) * 128 + rloc) * EMBED + h * HDIM;
#pragma unroll
                for (int nt = 0; nt < 4; ++nt) {
                    const int col = warp_n * 32 + nt * 8 + (lane & 3) * 2;
                    float f0 = acc[mt][nt][hh * 2 + 0] * dv;
                    float f1 = acc[mt][nt][hh * 2 + 1] * dv;
                    *reinterpret_cast<__half2*>(atH + ob + col) = __floats2half2_rn(f0, f1);
                }
            }
        }
        if (t2 == 0) __syncthreads();   // dinv_s reuse barrier
    }
}

// ---------------------------------------------------------------------------
// launch
// ---------------------------------------------------------------------------
extern "C" void kernel_launch(void* const* d_in, const int* in_sizes, int n_in,
                              void* d_out, int out_size)
{
    const float* query   = (const float*)d_in[0];
    const float* key_    = (const float*)d_in[1];
    const float* value   = (const float*)d_in[2];
    const float* Wq_down = (const float*)d_in[3];
    const float* Wq_up   = (const float*)d_in[4];
    const float* bq_up   = (const float*)d_in[5];
    const float* Wk_down = (const float*)d_in[6];
    const float* Wk_up   = (const float*)d_in[7];
    const float* bk_up   = (const float*)d_in[8];
    const float* Wv_down = (const float*)d_in[9];
    const float* Wv_up   = (const float*)d_in[10];
    const float* bv_up   = (const float*)d_in[11];
    const float* Wo      = (const float*)d_in[12];
    const float* bo      = (const float*)d_in[13];
    float* out = (float*)d_out;

    __half *QH, *KH, *VH, *atH, *kvTh;
    float *KVKS;
    cudaGetSymbolAddress((void**)&QH,   g_QH);
    cudaGetSymbolAddress((void**)&KH,   g_KH);
    cudaGetSymbolAddress((void**)&VH,   g_VH);
    cudaGetSymbolAddress((void**)&atH,  g_atH);
    cudaGetSymbolAddress((void**)&kvTh, g_kvTh);
    cudaGetSymbolAddress((void**)&KVKS, g_kvks);
    float* KV = KVKS;
    float* KS = KVKS + KV_ELEMS;

    cudaFuncSetAttribute((const void*)gemm_fused<0>, cudaFuncAttributeMaxDynamicSharedMemorySize, SMEM_GEMM);
    cudaFuncSetAttribute((const void*)gemm_fused<1>, cudaFuncAttributeMaxDynamicSharedMemorySize, SMEM_GEMM);
    cudaFuncSetAttribute((const void*)gemm_fused<2>, cudaFuncAttributeMaxDynamicSharedMemorySize, SMEM_GEMM);

    // one-time side stream + events (created on first call, before capture)
    static cudaStream_t s2 = nullptr;
    static cudaEvent_t evFork = nullptr, evJoin = nullptr;
    if (s2 == nullptr) {
        cudaStreamCreateWithFlags(&s2, cudaStreamNonBlocking);
        cudaEventCreateWithFlags(&evFork, cudaEventDisableTiming);
        cudaEventCreateWithFlags(&evJoin, cudaEventDisableTiming);
    }

    const dim3 blk(256);

    // fork: weights convert + accumulator zero on side stream,
    //       activation convert on main stream
    cudaEventRecord(evFork, 0);
    cudaStreamWaitEvent(s2, evFork, 0);
    wcvt_kernel<<<(6 * WSEG4 + EMBED*EMBED/4 + 255) / 256, blk, 0, s2>>>(
        Wq_down, Wq_up, Wk_down, Wk_up, Wv_down, Wv_up, Wo);
    {
        const int nz = KV_ELEMS + KS_ELEMS;
        zero_kernel<<<(nz + 255) / 256, blk, 0, s2>>>(KVKS, nz);
    }
    cudaEventRecord(evJoin, s2);

    cvt3_kernel<<<dim3(MTOK * EMBED / 8 / 256, 3), blk>>>(query, key_, value);

    // join before GEMMs (need weights + zeroed accumulators)
    cudaStreamWaitEvent(0, evJoin, 0);

    // down projections (one launch, z = q/k/v)
    gemm_fused<0><<<dim3(RANK / 128, MTOK / 128, 3), blk, SMEM_GEMM>>>(
        nullptr, nullptr, nullptr, nullptr);
    // up projections (one launch, z = q/k/v; elu for q,k; ksum fused for z==1)
    gemm_fused<1><<<dim3(EMBED / 128, MTOK / 128, 3), blk, SMEM_GEMM>>>(
        bq_up, bk_up, bv_up, nullptr);

    // kv (MMA)
    kv_mma_kernel<<<dim3(BH, KVNCH), blk>>>(KH, VH, KV);
    kvT_cvt_kernel<<<BH, blk>>>(KV, kvTh);

    // attention numerator (MMA) + fused denom + divide (2 tiles/CTA)
    attn_mma_kernel<<<dim3(BH, Nseq / 256), blk>>>(QH, kvTh, KS, atH);

    // output projection (fp32 out)
    gemm_fused<2><<<dim3(EMBED / 128, MTOK / 128, 1), blk, SMEM_GEMM>>>(
        bo, nullptr, nullptr, out);
}

// round 16
// speedup vs baseline: 1.1623x; 1.0099x over previous
#include <cuda_runtime.h>
#include <cuda_fp16.h>
#include <cstdint>

// ---------------------------------------------------------------------------
// Problem constants
// ---------------------------------------------------------------------------
#define Bv     4
#define Nseq   8192
#define EMBED  1024
#define HEADS  16
#define HDIM   64
#define RANK   512
#define MTOK   (Bv * Nseq)          // 32768
#define BH     (Bv * HEADS)         // 64

// ---------------------------------------------------------------------------
// Scratch (__device__ globals; allocation forbidden)
// ---------------------------------------------------------------------------
__device__ __half g_inH3[(size_t)3 * MTOK * EMBED];
__device__ __half g_yH3 [(size_t)3 * MTOK * RANK];
__device__ __half g_QH [MTOK * EMBED];
__device__ __half g_KH [MTOK * EMBED];
__device__ __half g_VH [MTOK * EMBED];
__device__ __half g_atH[MTOK * EMBED];

#define W_QD 0
#define W_QU (W_QD + RANK*EMBED)
#define W_KD (W_QU + EMBED*RANK)
#define W_KU (W_KD + RANK*EMBED)
#define W_VD (W_KU + EMBED*RANK)
#define W_VU (W_VD + RANK*EMBED)
#define W_O  (W_VU + EMBED*RANK)
#define W_TOT (W_O + EMBED*EMBED)
__device__ __half g_wH[W_TOT];

#define KV_ELEMS (BH * HDIM * HDIM)
#define KS_ELEMS (BH * HDIM)
__device__ float  g_kvks[KV_ELEMS + KS_ELEMS];
__device__ __half g_kvTh[KV_ELEMS];

// ---------------------------------------------------------------------------
// helpers
// ---------------------------------------------------------------------------
__device__ __forceinline__ uint32_t smem_u32(const void* p) {
    uint32_t a;
    asm("{ .reg .u64 t; cvta.to.shared.u64 t, %1; cvt.u32.u64 %0, t; }"
        : "=r"(a) : "l"(p));
    return a;
}

__device__ __forceinline__ void ldsm4(uint32_t* r, uint32_t addr) {
    asm volatile("ldmatrix.sync.aligned.m8n8.x4.shared.b16 {%0,%1,%2,%3}, [%4];"
        : "=r"(r[0]), "=r"(r[1]), "=r"(r[2]), "=r"(r[3]) : "r"(addr));
}

__device__ __forceinline__ void ldsm4t(uint32_t* r, uint32_t addr) {
    asm volatile("ldmatrix.sync.aligned.m8n8.x4.trans.shared.b16 {%0,%1,%2,%3}, [%4];"
        : "=r"(r[0]), "=r"(r[1]), "=r"(r[2]), "=r"(r[3]) : "r"(addr));
}

__device__ __forceinline__ void mma16816(float* c, const uint32_t* a, const uint32_t* b) {
    asm volatile("mma.sync.aligned.m16n8k16.row.col.f32.f16.f16.f32 "
        "{%0,%1,%2,%3}, {%4,%5,%6,%7}, {%8,%9}, {%0,%1,%2,%3};"
        : "+f"(c[0]), "+f"(c[1]), "+f"(c[2]), "+f"(c[3])
        : "r"(a[0]), "r"(a[1]), "r"(a[2]), "r"(a[3]), "r"(b[0]), "r"(b[1]));
}

#define CP_ASYNC16(so, ga) \
    asm volatile("cp.async.cg.shared.global [%0], [%1], 16;\n" :: "r"(so), "l"(ga))
#define CP_COMMIT() asm volatile("cp.async.commit_group;\n" ::: "memory")
#define CP_WAIT(n)  asm volatile("cp.async.wait_group %0;\n" :: "n"(n) : "memory")

// ---------------------------------------------------------------------------
// cvt1: one fp32 tensor -> fp16 slice z of g_inH3
// ---------------------------------------------------------------------------
__global__ void cvt1_kernel(const float* __restrict__ x, int z)
{
    __half* dst = g_inH3 + (size_t)z * (MTOK * EMBED);
    const int i = blockIdx.x * 256 + threadIdx.x;
    const float4* xp = reinterpret_cast<const float4*>(x) + 2 * (size_t)i;
    float4 a = xp[0], b = xp[1];
    __half2 h0 = __floats2half2_rn(a.x, a.y);
    __half2 h1 = __floats2half2_rn(a.z, a.w);
    __half2 h2 = __floats2half2_rn(b.x, b.y);
    __half2 h3 = __floats2half2_rn(b.z, b.w);
    uint4 o;
    o.x = *reinterpret_cast<uint32_t*>(&h0);
    o.y = *reinterpret_cast<uint32_t*>(&h1);
    o.z = *reinterpret_cast<uint32_t*>(&h2);
    o.w = *reinterpret_cast<uint32_t*>(&h3);
    reinterpret_cast<uint4*>(dst)[i] = o;
}

// ---------------------------------------------------------------------------
// wcvt: all 7 weights fp32 -> fp16 in one launch
// ---------------------------------------------------------------------------
#define WSEG4 (RANK * EMBED / 4)
__global__ void wcvt_kernel(const float* __restrict__ p0, const float* __restrict__ p1,
                            const float* __restrict__ p2, const float* __restrict__ p3,
                            const float* __restrict__ p4, const float* __restrict__ p5,
                            const float* __restrict__ p6)
{
    const int i = blockIdx.x * 256 + threadIdx.x;
    int seg, off;
    if (i >= 6 * WSEG4) { seg = 6; off = i - 6 * WSEG4; }
    else                { seg = i / WSEG4; off = i % WSEG4; }
    const float* ps[7] = {p0, p1, p2, p3, p4, p5, p6};
    float4 v = reinterpret_cast<const float4*>(ps[seg])[off];
    __half2* yp = reinterpret_cast<__half2*>(g_wH) + 2 * (size_t)i;
    yp[0] = __floats2half2_rn(v.x, v.y);
    yp[1] = __floats2half2_rn(v.z, v.w);
}

// ---------------------------------------------------------------------------
// fused mma.sync fp16 NT GEMM. Tile 128x128, BK=64, 8 warps, 3-stage, 2 CTA/SM.
// KIND 0: down (z = blockIdx.z + zoff). KIND 1: up3 (bias, elu for z<2; ksum z==1).
// KIND 2: Wo (fp32 + bias)
// ---------------------------------------------------------------------------
#define BKC        64
#define RSTRIDE_B  144
#define A_TILE_BY  (128 * RSTRIDE_B)
#define B_TILE_BY  (128 * RSTRIDE_B)
#define STAGE_BY   (A_TILE_BY + B_TILE_BY)
#define NSTAGE     3
#define SMEM_GEMM  (NSTAGE * STAGE_BY)      // 110592
#define OFF_A      0
#define OFF_B      A_TILE_BY

__device__ __forceinline__ void load_stage_mma(
    uint32_t sb, int tid, int s, int k0,
    const __half* __restrict__ A, const __half* __restrict__ B,
    int K, int aRow0, int bRow0)
{
    const uint32_t stage = sb + (uint32_t)s * STAGE_BY;
#pragma unroll
    for (int i = 0; i < 8; ++i) {
        int idx = tid + i * 256;
        int row = (idx & 1023) >> 3;
        int cb  = idx & 7;
        const __half* gp;
        int r0;
        uint32_t tbase;
        if (idx < 1024) { gp = A; r0 = aRow0; tbase = OFF_A; }
        else            { gp = B; r0 = bRow0; tbase = OFF_B; }
        const void* ga = gp + (size_t)(r0 + row) * K + k0 + cb * 8;
        uint32_t so = stage + tbase + (uint32_t)row * RSTRIDE_B + cb * 16;
        CP_ASYNC16(so, ga);
    }
    CP_COMMIT();
}

template <int KIND>
__global__ __launch_bounds__(256, 2) void gemm_fused(
    const float* __restrict__ b0, const float* __restrict__ b1,
    const float* __restrict__ b2, float* __restrict__ outF, int zoff)
{
    constexpr int NN = (KIND == 0) ? RANK : EMBED;
    constexpr int KK = (KIND == 0) ? EMBED : ((KIND == 1) ? RANK : EMBED);

    extern __shared__ char smem[];
    __shared__ float ksred[128];
    const uint32_t sb = smem_u32(smem);
    const int tid = threadIdx.x;
    const int wid = tid >> 5;
    const int lane = tid & 31;
    const int bn = blockIdx.x, bm = blockIdx.y;
    const int z = (KIND == 2) ? 0 : (blockIdx.z + zoff);
    const int warp_m = wid >> 2;
    const int warp_n = wid & 3;
    const int aRow0 = bm * 128, bRow0 = bn * 128;

    const __half* A;
    const __half* B;
    __half* Ch = nullptr;
    const float* bias = nullptr;
    bool elu = false;
    if (KIND == 0) {
        A = g_inH3 + (size_t)z * (MTOK * EMBED);
        B = g_wH + (size_t)z * (2 * RANK * EMBED);
        Ch = g_yH3 + (size_t)z * (MTOK * RANK);
    } else if (KIND == 1) {
        A = g_yH3 + (size_t)z * (MTOK * RANK);
        B = g_wH + W_QU + (size_t)z * (2 * RANK * EMBED);
        bias = (z == 0) ? b0 : (z == 1) ? b1 : b2;
        Ch = (z == 0) ? g_QH : (z == 1) ? g_KH : g_VH;
        elu = (z < 2);
    } else {
        A = g_atH;
        B = g_wH + W_O;
        bias = b0;
    }

    float acc[4][4][4];
#pragma unroll
    for (int mt = 0; mt < 4; ++mt)
#pragma unroll
        for (int nt = 0; nt < 4; ++nt)
#pragma unroll
            for (int j = 0; j < 4; ++j) acc[mt][nt][j] = 0.f;

    const int nch = KK / BKC;

    load_stage_mma(sb, tid, 0, 0,   A, B, KK, aRow0, bRow0);
    load_stage_mma(sb, tid, 1, BKC, A, B, KK, aRow0, bRow0);

    const int a_r = lane & 15;
    const int a_c = (lane >> 4) * 8;
    const int b_n = ((lane >> 4) << 3) + (lane & 7);
    const int b_k = ((lane >> 3) & 1) * 8;

    for (int c = 0; c < nch; ++c) {
        if (c == nch - 1) { CP_WAIT(0); } else { CP_WAIT(1); }
        __syncthreads();

        if (c + 2 < nch)
            load_stage_mma(sb, tid, (c + 2) % NSTAGE, (c + 2) * BKC,
                           A, B, KK, aRow0, bRow0);

        const uint32_t st = sb + (uint32_t)(c % NSTAGE) * STAGE_BY;
#pragma unroll
        for (int ks = 0; ks < 4; ++ks) {
            const int k0 = ks * 16;
            uint32_t ar[4][4];
#pragma unroll
            for (int mt = 0; mt < 4; ++mt) {
                uint32_t off = (uint32_t)(warp_m * 64 + mt * 16 + a_r) * RSTRIDE_B
                             + (uint32_t)(k0 + a_c) * 2;
                ldsm4(ar[mt], st + OFF_A + off);
            }
            uint32_t br[4][2];
#pragma unroll
            for (int nt2 = 0; nt2 < 2; ++nt2) {
                uint32_t off = (uint32_t)(warp_n * 32 + nt2 * 16 + b_n) * RSTRIDE_B
                             + (uint32_t)(k0 + b_k) * 2;
                uint32_t t4[4];
                ldsm4(t4, st + OFF_B + off);
                br[nt2*2][0] = t4[0]; br[nt2*2][1] = t4[1];
                br[nt2*2+1][0] = t4[2]; br[nt2*2+1][1] = t4[3];
            }
#pragma unroll
            for (int mt = 0; mt < 4; ++mt)
#pragma unroll
                for (int nt = 0; nt < 4; ++nt)
                    mma16816(acc[mt][nt], ar[mt], br[nt]);
        }
    }

    // epilogue (+ fused ksum partials for KIND 1, z == 1)
    const bool do_ks = (KIND == 1) && (z == 1);
    if (do_ks) {
        if (tid < 128) ksred[tid] = 0.f;
        __syncthreads();
    }
    float ksp[4][2];
#pragma unroll
    for (int nt = 0; nt < 4; ++nt) { ksp[nt][0] = 0.f; ksp[nt][1] = 0.f; }

#pragma unroll
    for (int mt = 0; mt < 4; ++mt) {
#pragma unroll
        for (int nt = 0; nt < 4; ++nt) {
            const int row0 = bm * 128 + warp_m * 64 + mt * 16 + (lane >> 2);
            const int col  = bn * 128 + warp_n * 32 + nt * 8 + (lane & 3) * 2;
#pragma unroll
            for (int h = 0; h < 2; ++h) {
                const int row = row0 + h * 8;
                float f0 = acc[mt][nt][h * 2 + 0];
                float f1 = acc[mt][nt][h * 2 + 1];
                if (KIND >= 1) {
                    f0 += __ldg(bias + col);
                    f1 += __ldg(bias + col + 1);
                }
                if (KIND == 1 && elu) {
                    f0 = (f0 > 0.f) ? (f0 + 1.f) : __expf(f0);
                    f1 = (f1 > 0.f) ? (f1 + 1.f) : __expf(f1);
                }
                if (do_ks) { ksp[nt][0] += f0; ksp[nt][1] += f1; }
                if (KIND == 2) {
                    *reinterpret_cast<float2*>(outF + (size_t)row * NN + col) =
                        make_float2(f0, f1);
                } else {
                    *reinterpret_cast<__half2*>(Ch + (size_t)row * NN + col) =
                        __floats2half2_rn(f0, f1);
                }
            }
        }
    }

    if (do_ks) {
#pragma unroll
        for (int nt = 0; nt < 4; ++nt) {
            const int cloc = warp_n * 32 + nt * 8 + (lane & 3) * 2;
            atomicAdd(&ksred[cloc],     ksp[nt][0]);
            atomicAdd(&ksred[cloc + 1], ksp[nt][1]);
        }
        __syncthreads();
        if (tid < 128) {
            const int gcol = bn * 128 + tid;
            const int bb = bm >> 6;
            const int bh = bb * 16 + (gcol >> 6);
            atomicAdd(g_kvks + KV_ELEMS + bh * 64 + (gcol & 63), ksred[tid]);
        }
    }
}

// ---------------------------------------------------------------------------
// zero kernel
// ---------------------------------------------------------------------------
__global__ void zero_kernel(float* __restrict__ p, int n)
{
    int i = blockIdx.x * blockDim.x + threadIdx.x;
    if (i < n) p[i] = 0.f;
}

// ---------------------------------------------------------------------------
// kv via MMA: kv[bh][d][e] += sum_n k[n,d]*v[n,e]
// ---------------------------------------------------------------------------
#define KVNCH   4
#define KVTOK   (Nseq / KVNCH)
#define KV_STR  144
#define KV_TILE (64 * KV_STR)
#define KV_STG  (2 * KV_TILE)

__global__ __launch_bounds__(256, 2) void kv_mma_kernel(
    const __half* __restrict__ KH, const __half* __restrict__ VH,
    float* __restrict__ kv)
{
    __shared__ char smem[3 * KV_STG];
    const uint32_t sb = smem_u32(smem);

    const int bh = blockIdx.x;
    const int b = bh >> 4, h = bh & 15;
    const int chunk = blockIdx.y;
    const int tid = threadIdx.x;
    const int wid = tid >> 5;
    const int lane = tid & 31;
    const int warp_m = wid >> 1;
    const int warp_n = wid & 1;

    const size_t tokBase = (size_t)b * Nseq + (size_t)chunk * KVTOK;

    const int atr = (lane & 7) + ((lane >> 4) << 3);
    const int atc = ((lane >> 3) & 1) * 16;
    const int btr = (lane & 7) + ((lane >> 3) & 1) * 8;
    const int btc = (lane >> 4) * 16;

    float acc[4][4];
#pragma unroll
    for (int nt = 0; nt < 4; ++nt)
#pragma unroll
        for (int j = 0; j < 4; ++j) acc[nt][j] = 0.f;

    const int niter = KVTOK / 64;

    auto load_tile = [&](int s, int it) {
        const uint32_t stage = sb + (uint32_t)s * KV_STG;
#pragma unroll
        for (int i = 0; i < 4; ++i) {
            int idx = tid + i * 256;
            int tile = idx >> 9;
            int w = idx & 511;
            int row = w >> 3, cb = w & 7;
            const __half* gp = tile ? VH : KH;
            const void* ga = gp + (tokBase + (size_t)it * 64 + row) * EMBED + h * HDIM + cb * 8;
            uint32_t so = stage + (uint32_t)tile * KV_TILE + (uint32_t)row * KV_STR + cb * 16;
            CP_ASYNC16(so, ga);
        }
        CP_COMMIT();
    };

    load_tile(0, 0);
    load_tile(1, 1);

    for (int it = 0; it < niter; ++it) {
        if (it == niter - 1) { CP_WAIT(0); } else { CP_WAIT(1); }
        __syncthreads();

        if (it + 2 < niter)
            load_tile((it + 2) % 3, it + 2);

        const uint32_t st = sb + (uint32_t)(it % 3) * KV_STG;
        const uint32_t kb = st;
        const uint32_t vb = st + KV_TILE;

#pragma unroll
        for (int ts = 0; ts < 4; ++ts) {
            const int t0 = ts * 16;
            uint32_t a4[4];
            ldsm4t(a4, kb + (uint32_t)(t0 + atr) * KV_STR
                      + (uint32_t)(warp_m * 32) + atc);
            uint32_t br[4][2];
#pragma unroll
            for (int nt2 = 0; nt2 < 2; ++nt2) {
                uint32_t t4[4];
                ldsm4t(t4, vb + (uint32_t)(t0 + btr) * KV_STR
                          + (uint32_t)(warp_n * 64 + nt2 * 32) + btc);
                br[nt2*2][0]   = t4[0]; br[nt2*2][1]   = t4[1];
                br[nt2*2+1][0] = t4[2]; br[nt2*2+1][1] = t4[3];
            }
#pragma unroll
            for (int nt = 0; nt < 4; ++nt)
                mma16816(acc[nt], a4, br[nt]);
        }
    }

    float* kvp = kv + (size_t)bh * (HDIM * HDIM);
#pragma unroll
    for (int nt = 0; nt < 4; ++nt) {
#pragma unroll
        for (int hh = 0; hh < 2; ++hh) {
            const int d = warp_m * 16 + (lane >> 2) + hh * 8;
            const int e = warp_n * 32 + nt * 8 + (lane & 3) * 2;
            atomicAdd(kvp + d * HDIM + e,     acc[nt][hh * 2 + 0]);
            atomicAdd(kvp + d * HDIM + e + 1, acc[nt][hh * 2 + 1]);
        }
    }
}

// ---------------------------------------------------------------------------
// kvT convert
// ---------------------------------------------------------------------------
__global__ __launch_bounds__(256) void kvT_cvt_kernel(
    const float* __restrict__ kv, __half* __restrict__ kvTh)
{
    const int bh = blockIdx.x;
    const int tid = threadIdx.x;
    __shared__ float s[64][65];
    for (int i = tid; i < 4096; i += 256)
        s[i >> 6][i & 63] = kv[(size_t)bh * 4096 + i];
    __syncthreads();
    for (int i = tid; i < 4096; i += 256) {
        const int e = i >> 6, d = i & 63;
        kvTh[(size_t)bh * 4096 + i] = __float2half(s[d][e]);
    }
}

// ---------------------------------------------------------------------------
// attn numerator via MMA + fused denominator; 2 token tiles per CTA
// ---------------------------------------------------------------------------
#define AT_STR 144
__global__ __launch_bounds__(256) void attn_mma_kernel(
    const __half* __restrict__ Qh, const __half* __restrict__ kvTh,
    const float* __restrict__ ksum, __half* __restrict__ atH)
{
    __shared__ char smem[2 * 128 * AT_STR + 64 * AT_STR];
    __shared__ float ks_s[64];
    __shared__ float dinv_s[128];
    const uint32_t sq0 = smem_u32(smem);
    const uint32_t sq1 = sq0 + 128 * AT_STR;
    const uint32_t skt = sq0 + 2 * 128 * AT_STR;

    const int bh = blockIdx.x;
    const int b = bh >> 4, h = bh & 15;
    const int tt0 = blockIdx.y * 2;
    const int tid = threadIdx.x;
    const int wid = tid >> 5;
    const int lane = tid & 31;
    const int warp_m = wid >> 1;
    const int warp_n = wid & 1;

#pragma unroll
    for (int i = 0; i < 4; ++i) {
        int idx = tid + i * 256;
        int row = idx >> 3, cb = idx & 7;
        const void* ga = Qh + ((size_t)b * Nseq + tt0 * 128 + row) * EMBED + h * HDIM + cb * 8;
        CP_ASYNC16(sq0 + (uint32_t)row * AT_STR + cb * 16, ga);
    }
#pragma unroll
    for (int i = 0; i < 2; ++i) {
        int idx = tid + i * 256;
        int row = idx >> 3, cb = idx & 7;
        const void* ga = kvTh + (size_t)bh * 4096 + row * 64 + cb * 8;
        CP_ASYNC16(skt + (uint32_t)row * AT_STR + cb * 16, ga);
    }
    CP_COMMIT();
#pragma unroll
    for (int i = 0; i < 4; ++i) {
        int idx = tid + i * 256;
        int row = idx >> 3, cb = idx & 7;
        const void* ga = Qh + ((size_t)b * Nseq + (tt0 + 1) * 128 + row) * EMBED + h * HDIM + cb * 8;
        CP_ASYNC16(sq1 + (uint32_t)row * AT_STR + cb * 16, ga);
    }
    CP_COMMIT();

    if (tid < 64) ks_s[tid] = ksum[bh * 64 + tid];

    const int a_r = lane & 15;
    const int a_c = (lane >> 4) * 8;
    const int b_n = ((lane >> 4) << 3) + (lane & 7);
    const int b_k = ((lane >> 3) & 1) * 8;

#pragma unroll
    for (int t2 = 0; t2 < 2; ++t2) {
        const uint32_t sq = (t2 == 0) ? sq0 : sq1;
        if (t2 == 0) { CP_WAIT(1); } else { CP_WAIT(0); }
        __syncthreads();

        if (tid < 128) {
            const uint32_t qrow = sq + (uint32_t)tid * AT_STR;
            float d = 0.f;
#pragma unroll
            for (int j = 0; j < 32; ++j) {
                uint32_t packed;
                asm volatile("ld.shared.b32 %0, [%1];" : "=r"(packed) : "r"(qrow + j * 4));
                __half2 q2 = *reinterpret_cast<__half2*>(&packed);
                float2 qf = __half22float2(q2);
                d = fmaf(qf.x, ks_s[2 * j], d);
                d = fmaf(qf.y, ks_s[2 * j + 1], d);
            }
            dinv_s[tid] = 1.0f / (d + 1e-6f);
        }
        __syncthreads();

        float acc[2][4][4];
#pragma unroll
        for (int mt = 0; mt < 2; ++mt)
#pragma unroll
            for (int nt = 0; nt < 4; ++nt)
#pragma unroll
                for (int j = 0; j < 4; ++j) acc[mt][nt][j] = 0.f;

#pragma unroll
        for (int ks = 0; ks < 4; ++ks) {
            const int k0 = ks * 16;
            uint32_t ar[2][4];
#pragma unroll
            for (int mt = 0; mt < 2; ++mt) {
                uint32_t off = (uint32_t)(warp_m * 32 + mt * 16 + a_r) * AT_STR
                             + (uint32_t)(k0 + a_c) * 2;
                ldsm4(ar[mt], sq + off);
            }
            uint32_t br[4][2];
#pragma unroll
            for (int nt2 = 0; nt2 < 2; ++nt2) {
                uint32_t off = (uint32_t)(warp_n * 32 + nt2 * 16 + b_n) * AT_STR
                             + (uint32_t)(k0 + b_k) * 2;
                uint32_t t4[4];
                ldsm4(t4, skt + off);
                br[nt2*2][0] = t4[0]; br[nt2*2][1] = t4[1];
                br[nt2*2+1][0] = t4[2]; br[nt2*2+1][1] = t4[3];
            }
#pragma unroll
            for (int mt = 0; mt < 2; ++mt)
#pragma unroll
                for (int nt = 0; nt < 4; ++nt)
                    mma16816(acc[mt][nt], ar[mt], br[nt]);
        }

#pragma unroll
        for (int mt = 0; mt < 2; ++mt) {
#pragma unroll
            for (int hh = 0; hh < 2; ++hh) {
                const int rloc = warp_m * 32 + mt * 16 + (lane >> 2) + hh * 8;
                const float dv = dinv_s[rloc];
                const size_t ob = ((size_t)b * Nseq + (tt0 + t2) * 128 + rloc) * EMBED + h * HDIM;
#pragma unroll
                for (int nt = 0; nt < 4; ++nt) {
                    const int col = warp_n * 32 + nt * 8 + (lane & 3) * 2;
                    float f0 = acc[mt][nt][hh * 2 + 0] * dv;
                    float f1 = acc[mt][nt][hh * 2 + 1] * dv;
                    *reinterpret_cast<__half2*>(atH + ob + col) = __floats2half2_rn(f0, f1);
                }
            }
        }
        if (t2 == 0) __syncthreads();
    }
}

// ---------------------------------------------------------------------------
// launch
// ---------------------------------------------------------------------------
extern "C" void kernel_launch(void* const* d_in, const int* in_sizes, int n_in,
                              void* d_out, int out_size)
{
    const float* query   = (const float*)d_in[0];
    const float* key_    = (const float*)d_in[1];
    const float* value   = (const float*)d_in[2];
    const float* Wq_down = (const float*)d_in[3];
    const float* Wq_up   = (const float*)d_in[4];
    const float* bq_up   = (const float*)d_in[5];
    const float* Wk_down = (const float*)d_in[6];
    const float* Wk_up   = (const float*)d_in[7];
    const float* bk_up   = (const float*)d_in[8];
    const float* Wv_down = (const float*)d_in[9];
    const float* Wv_up   = (const float*)d_in[10];
    const float* bv_up   = (const float*)d_in[11];
    const float* Wo      = (const float*)d_in[12];
    const float* bo      = (const float*)d_in[13];
    float* out = (float*)d_out;

    __half *QH, *KH, *VH, *atH, *kvTh;
    float *KVKS;
    cudaGetSymbolAddress((void**)&QH,   g_QH);
    cudaGetSymbolAddress((void**)&KH,   g_KH);
    cudaGetSymbolAddress((void**)&VH,   g_VH);
    cudaGetSymbolAddress((void**)&atH,  g_atH);
    cudaGetSymbolAddress((void**)&kvTh, g_kvTh);
    cudaGetSymbolAddress((void**)&KVKS, g_kvks);
    float* KV = KVKS;
    float* KS = KVKS + KV_ELEMS;

    cudaFuncSetAttribute((const void*)gemm_fused<0>, cudaFuncAttributeMaxDynamicSharedMemorySize, SMEM_GEMM);
    cudaFuncSetAttribute((const void*)gemm_fused<1>, cudaFuncAttributeMaxDynamicSharedMemorySize, SMEM_GEMM);
    cudaFuncSetAttribute((const void*)gemm_fused<2>, cudaFuncAttributeMaxDynamicSharedMemorySize, SMEM_GEMM);

    static cudaStream_t s2 = nullptr;
    static cudaEvent_t evFork = nullptr, evJoin = nullptr;
    if (s2 == nullptr) {
        cudaStreamCreateWithFlags(&s2, cudaStreamNonBlocking);
        cudaEventCreateWithFlags(&evFork, cudaEventDisableTiming);
        cudaEventCreateWithFlags(&evJoin, cudaEventDisableTiming);
    }

    const dim3 blk(256);
    const int nCvtBlk = MTOK * EMBED / 8 / 256;   // 16384

    // weights first on main (needed by down(q))
    wcvt_kernel<<<(6 * WSEG4 + EMBED*EMBED/4 + 255) / 256, blk>>>(
        Wq_down, Wq_up, Wk_down, Wk_up, Wv_down, Wv_up, Wo);

    // fork: k/v converts + accumulator zero on side stream,
    //       q convert + down(q) on main — runs concurrently
    cudaEventRecord(evFork, 0);
    cudaStreamWaitEvent(s2, evFork, 0);
    {
        const int nz = KV_ELEMS + KS_ELEMS;
        zero_kernel<<<(nz + 255) / 256, blk, 0, s2>>>(KVKS, nz);
    }
    cvt1_kernel<<<nCvtBlk, blk, 0, s2>>>(key_,   1);
    cvt1_kernel<<<nCvtBlk, blk, 0, s2>>>(value,  2);
    cudaEventRecord(evJoin, s2);

    cvt1_kernel<<<nCvtBlk, blk>>>(query, 0);
    gemm_fused<0><<<dim3(RANK / 128, MTOK / 128, 1), blk, SMEM_GEMM>>>(
        nullptr, nullptr, nullptr, nullptr, 0);          // down(q)

    // join: down(k,v) needs cvt(k), cvt(v); up(k) epilogue needs zeroed ksum
    cudaStreamWaitEvent(0, evJoin, 0);

    gemm_fused<0><<<dim3(RANK / 128, MTOK / 128, 2), blk, SMEM_GEMM>>>(
        nullptr, nullptr, nullptr, nullptr, 1);          // down(k,v)

    // up projections (z = q/k/v; elu for q,k; ksum fused for z==1)
    gemm_fused<1><<<dim3(EMBED / 128, MTOK / 128, 3), blk, SMEM_GEMM>>>(
        bq_up, bk_up, bv_up, nullptr, 0);

    // kv (MMA)
    kv_mma_kernel<<<dim3(BH, KVNCH), blk>>>(KH, VH, KV);
    kvT_cvt_kernel<<<BH, blk>>>(KV, kvTh);

    // attention numerator (MMA) + fused denom + divide (2 tiles/CTA)
    attn_mma_kernel<<<dim3(BH, Nseq / 256), blk>>>(QH, kvTh, KS, atH);

    // output projection (fp32 out)
    gemm_fused<2><<<dim3(EMBED / 128, MTOK / 128, 1), blk, SMEM_GEMM>>>(
        bo, nullptr, nullptr, out, 0);
}

// round 17
// speedup vs baseline: 1.1661x; 1.0033x over previous
#include <cuda_runtime.h>
#include <cuda_fp16.h>
#include <cstdint>

// ---------------------------------------------------------------------------
// Problem constants
// ---------------------------------------------------------------------------
#define Bv     4
#define Nseq   8192
#define EMBED  1024
#define HEADS  16
#define HDIM   64
#define RANK   512
#define MTOK   (Bv * Nseq)          // 32768
#define BH     (Bv * HEADS)         // 64

// ---------------------------------------------------------------------------
// Scratch (__device__ globals; allocation forbidden)
// ---------------------------------------------------------------------------
__device__ __half g_inH3[(size_t)3 * MTOK * EMBED];
__device__ __half g_yH3 [(size_t)3 * MTOK * RANK];
__device__ __half g_QH [MTOK * EMBED];
__device__ __half g_KH [MTOK * EMBED];
__device__ __half g_VH [MTOK * EMBED];
__device__ __half g_atH[MTOK * EMBED];

#define W_QD 0
#define W_QU (W_QD + RANK*EMBED)
#define W_KD (W_QU + EMBED*RANK)
#define W_KU (W_KD + RANK*EMBED)
#define W_VD (W_KU + EMBED*RANK)
#define W_VU (W_VD + RANK*EMBED)
#define W_O  (W_VU + EMBED*RANK)
#define W_TOT (W_O + EMBED*EMBED)
__device__ __half g_wH[W_TOT];

#define KV_ELEMS (BH * HDIM * HDIM)
#define KS_ELEMS (BH * HDIM)
__device__ float  g_kvks[KV_ELEMS + KS_ELEMS];
__device__ __half g_kvTh[KV_ELEMS];

// ---------------------------------------------------------------------------
// helpers
// ---------------------------------------------------------------------------
__device__ __forceinline__ uint32_t smem_u32(const void* p) {
    uint32_t a;
    asm("{ .reg .u64 t; cvta.to.shared.u64 t, %1; cvt.u32.u64 %0, t; }"
        : "=r"(a) : "l"(p));
    return a;
}

__device__ __forceinline__ void ldsm4(uint32_t* r, uint32_t addr) {
    asm volatile("ldmatrix.sync.aligned.m8n8.x4.shared.b16 {%0,%1,%2,%3}, [%4];"
        : "=r"(r[0]), "=r"(r[1]), "=r"(r[2]), "=r"(r[3]) : "r"(addr));
}

__device__ __forceinline__ void ldsm4t(uint32_t* r, uint32_t addr) {
    asm volatile("ldmatrix.sync.aligned.m8n8.x4.trans.shared.b16 {%0,%1,%2,%3}, [%4];"
        : "=r"(r[0]), "=r"(r[1]), "=r"(r[2]), "=r"(r[3]) : "r"(addr));
}

__device__ __forceinline__ void mma16816(float* c, const uint32_t* a, const uint32_t* b) {
    asm volatile("mma.sync.aligned.m16n8k16.row.col.f32.f16.f16.f32 "
        "{%0,%1,%2,%3}, {%4,%5,%6,%7}, {%8,%9}, {%0,%1,%2,%3};"
        : "+f"(c[0]), "+f"(c[1]), "+f"(c[2]), "+f"(c[3])
        : "r"(a[0]), "r"(a[1]), "r"(a[2]), "r"(a[3]), "r"(b[0]), "r"(b[1]));
}

#define CP_ASYNC16(so, ga) \
    asm volatile("cp.async.cg.shared.global [%0], [%1], 16;\n" :: "r"(so), "l"(ga))
#define CP_COMMIT() asm volatile("cp.async.commit_group;\n" ::: "memory")
#define CP_WAIT(n)  asm volatile("cp.async.wait_group %0;\n" :: "n"(n) : "memory")

// ---------------------------------------------------------------------------
// cvt1: one fp32 tensor -> fp16 slice z of g_inH3
// ---------------------------------------------------------------------------
__global__ void cvt1_kernel(const float* __restrict__ x, int z)
{
    __half* dst = g_inH3 + (size_t)z * (MTOK * EMBED);
    const int i = blockIdx.x * 256 + threadIdx.x;
    const float4* xp = reinterpret_cast<const float4*>(x) + 2 * (size_t)i;
    float4 a = xp[0], b = xp[1];
    __half2 h0 = __floats2half2_rn(a.x, a.y);
    __half2 h1 = __floats2half2_rn(a.z, a.w);
    __half2 h2 = __floats2half2_rn(b.x, b.y);
    __half2 h3 = __floats2half2_rn(b.z, b.w);
    uint4 o;
    o.x = *reinterpret_cast<uint32_t*>(&h0);
    o.y = *reinterpret_cast<uint32_t*>(&h1);
    o.z = *reinterpret_cast<uint32_t*>(&h2);
    o.w = *reinterpret_cast<uint32_t*>(&h3);
    reinterpret_cast<uint4*>(dst)[i] = o;
}

// ---------------------------------------------------------------------------
// wcvt: all 7 weights fp32 -> fp16 in one launch
// ---------------------------------------------------------------------------
#define WSEG4 (RANK * EMBED / 4)
__global__ void wcvt_kernel(const float* __restrict__ p0, const float* __restrict__ p1,
                            const float* __restrict__ p2, const float* __restrict__ p3,
                            const float* __restrict__ p4, const float* __restrict__ p5,
                            const float* __restrict__ p6)
{
    const int i = blockIdx.x * 256 + threadIdx.x;
    int seg, off;
    if (i >= 6 * WSEG4) { seg = 6; off = i - 6 * WSEG4; }
    else                { seg = i / WSEG4; off = i % WSEG4; }
    const float* ps[7] = {p0, p1, p2, p3, p4, p5, p6};
    float4 v = reinterpret_cast<const float4*>(ps[seg])[off];
    __half2* yp = reinterpret_cast<__half2*>(g_wH) + 2 * (size_t)i;
    yp[0] = __floats2half2_rn(v.x, v.y);
    yp[1] = __floats2half2_rn(v.z, v.w);
}

// ---------------------------------------------------------------------------
// fused mma.sync fp16 NT GEMM. Tile 128x128, BK=64, 8 warps, 3-stage, 2 CTA/SM.
// KIND 0: down (z = blockIdx.z + zoff). KIND 1: up (z = blockIdx.z + zoff;
// bias, elu for z<2; ksum fused for z==1). KIND 2: Wo (fp32 + bias)
// ---------------------------------------------------------------------------
#define BKC        64
#define RSTRIDE_B  144
#define A_TILE_BY  (128 * RSTRIDE_B)
#define B_TILE_BY  (128 * RSTRIDE_B)
#define STAGE_BY   (A_TILE_BY + B_TILE_BY)
#define NSTAGE     3
#define SMEM_GEMM  (NSTAGE * STAGE_BY)      // 110592
#define OFF_A      0
#define OFF_B      A_TILE_BY

__device__ __forceinline__ void load_stage_mma(
    uint32_t sb, int tid, int s, int k0,
    const __half* __restrict__ A, const __half* __restrict__ B,
    int K, int aRow0, int bRow0)
{
    const uint32_t stage = sb + (uint32_t)s * STAGE_BY;
#pragma unroll
    for (int i = 0; i < 8; ++i) {
        int idx = tid + i * 256;
        int row = (idx & 1023) >> 3;
        int cb  = idx & 7;
        const __half* gp;
        int r0;
        uint32_t tbase;
        if (idx < 1024) { gp = A; r0 = aRow0; tbase = OFF_A; }
        else            { gp = B; r0 = bRow0; tbase = OFF_B; }
        const void* ga = gp + (size_t)(r0 + row) * K + k0 + cb * 8;
        uint32_t so = stage + tbase + (uint32_t)row * RSTRIDE_B + cb * 16;
        CP_ASYNC16(so, ga);
    }
    CP_COMMIT();
}

template <int KIND>
__global__ __launch_bounds__(256, 2) void gemm_fused(
    const float* __restrict__ b0, const float* __restrict__ b1,
    const float* __restrict__ b2, float* __restrict__ outF, int zoff)
{
    constexpr int NN = (KIND == 0) ? RANK : EMBED;
    constexpr int KK = (KIND == 0) ? EMBED : ((KIND == 1) ? RANK : EMBED);

    extern __shared__ char smem[];
    __shared__ float ksred[128];
    const uint32_t sb = smem_u32(smem);
    const int tid = threadIdx.x;
    const int wid = tid >> 5;
    const int lane = tid & 31;
    const int bn = blockIdx.x, bm = blockIdx.y;
    const int z = (KIND == 2) ? 0 : (blockIdx.z + zoff);
    const int warp_m = wid >> 2;
    const int warp_n = wid & 3;
    const int aRow0 = bm * 128, bRow0 = bn * 128;

    const __half* A;
    const __half* B;
    __half* Ch = nullptr;
    const float* bias = nullptr;
    bool elu = false;
    if (KIND == 0) {
        A = g_inH3 + (size_t)z * (MTOK * EMBED);
        B = g_wH + (size_t)z * (2 * RANK * EMBED);
        Ch = g_yH3 + (size_t)z * (MTOK * RANK);
    } else if (KIND == 1) {
        A = g_yH3 + (size_t)z * (MTOK * RANK);
        B = g_wH + W_QU + (size_t)z * (2 * RANK * EMBED);
        bias = (z == 0) ? b0 : (z == 1) ? b1 : b2;
        Ch = (z == 0) ? g_QH : (z == 1) ? g_KH : g_VH;
        elu = (z < 2);
    } else {
        A = g_atH;
        B = g_wH + W_O;
        bias = b0;
    }

    float acc[4][4][4];
#pragma unroll
    for (int mt = 0; mt < 4; ++mt)
#pragma unroll
        for (int nt = 0; nt < 4; ++nt)
#pragma unroll
            for (int j = 0; j < 4; ++j) acc[mt][nt][j] = 0.f;

    const int nch = KK / BKC;

    load_stage_mma(sb, tid, 0, 0,   A, B, KK, aRow0, bRow0);
    load_stage_mma(sb, tid, 1, BKC, A, B, KK, aRow0, bRow0);

    const int a_r = lane & 15;
    const int a_c = (lane >> 4) * 8;
    const int b_n = ((lane >> 4) << 3) + (lane & 7);
    const int b_k = ((lane >> 3) & 1) * 8;

    for (int c = 0; c < nch; ++c) {
        if (c == nch - 1) { CP_WAIT(0); } else { CP_WAIT(1); }
        __syncthreads();

        if (c + 2 < nch)
            load_stage_mma(sb, tid, (c + 2) % NSTAGE, (c + 2) * BKC,
                           A, B, KK, aRow0, bRow0);

        const uint32_t st = sb + (uint32_t)(c % NSTAGE) * STAGE_BY;
#pragma unroll
        for (int ks = 0; ks < 4; ++ks) {
            const int k0 = ks * 16;
            uint32_t ar[4][4];
#pragma unroll
            for (int mt = 0; mt < 4; ++mt) {
                uint32_t off = (uint32_t)(warp_m * 64 + mt * 16 + a_r) * RSTRIDE_B
                             + (uint32_t)(k0 + a_c) * 2;
                ldsm4(ar[mt], st + OFF_A + off);
            }
            uint32_t br[4][2];
#pragma unroll
            for (int nt2 = 0; nt2 < 2; ++nt2) {
                uint32_t off = (uint32_t)(warp_n * 32 + nt2 * 16 + b_n) * RSTRIDE_B
                             + (uint32_t)(k0 + b_k) * 2;
                uint32_t t4[4];
                ldsm4(t4, st + OFF_B + off);
                br[nt2*2][0] = t4[0]; br[nt2*2][1] = t4[1];
                br[nt2*2+1][0] = t4[2]; br[nt2*2+1][1] = t4[3];
            }
#pragma unroll
            for (int mt = 0; mt < 4; ++mt)
#pragma unroll
                for (int nt = 0; nt < 4; ++nt)
                    mma16816(acc[mt][nt], ar[mt], br[nt]);
        }
    }

    // epilogue (+ fused ksum partials for KIND 1, z == 1)
    const bool do_ks = (KIND == 1) && (z == 1);
    if (do_ks) {
        if (tid < 128) ksred[tid] = 0.f;
        __syncthreads();
    }
    float ksp[4][2];
#pragma unroll
    for (int nt = 0; nt < 4; ++nt) { ksp[nt][0] = 0.f; ksp[nt][1] = 0.f; }

#pragma unroll
    for (int mt = 0; mt < 4; ++mt) {
#pragma unroll
        for (int nt = 0; nt < 4; ++nt) {
            const int row0 = bm * 128 + warp_m * 64 + mt * 16 + (lane >> 2);
            const int col  = bn * 128 + warp_n * 32 + nt * 8 + (lane & 3) * 2;
#pragma unroll
            for (int h = 0; h < 2; ++h) {
                const int row = row0 + h * 8;
                float f0 = acc[mt][nt][h * 2 + 0];
                float f1 = acc[mt][nt][h * 2 + 1];
                if (KIND >= 1) {
                    f0 += __ldg(bias + col);
                    f1 += __ldg(bias + col + 1);
                }
                if (KIND == 1 && elu) {
                    f0 = (f0 > 0.f) ? (f0 + 1.f) : __expf(f0);
                    f1 = (f1 > 0.f) ? (f1 + 1.f) : __expf(f1);
                }
                if (do_ks) { ksp[nt][0] += f0; ksp[nt][1] += f1; }
                if (KIND == 2) {
                    *reinterpret_cast<float2*>(outF + (size_t)row * NN + col) =
                        make_float2(f0, f1);
                } else {
                    *reinterpret_cast<__half2*>(Ch + (size_t)row * NN + col) =
                        __floats2half2_rn(f0, f1);
                }
            }
        }
    }

    if (do_ks) {
#pragma unroll
        for (int nt = 0; nt < 4; ++nt) {
            const int cloc = warp_n * 32 + nt * 8 + (lane & 3) * 2;
            atomicAdd(&ksred[cloc],     ksp[nt][0]);
            atomicAdd(&ksred[cloc + 1], ksp[nt][1]);
        }
        __syncthreads();
        if (tid < 128) {
            const int gcol = bn * 128 + tid;
            const int bb = bm >> 6;
            const int bh = bb * 16 + (gcol >> 6);
            atomicAdd(g_kvks + KV_ELEMS + bh * 64 + (gcol & 63), ksred[tid]);
        }
    }
}

// ---------------------------------------------------------------------------
// zero kernel
// ---------------------------------------------------------------------------
__global__ void zero_kernel(float* __restrict__ p, int n)
{
    int i = blockIdx.x * blockDim.x + threadIdx.x;
    if (i < n) p[i] = 0.f;
}

// ---------------------------------------------------------------------------
// kv via MMA: kv[bh][d][e] += sum_n k[n,d]*v[n,e]
// ---------------------------------------------------------------------------
#define KVNCH   4
#define KVTOK   (Nseq / KVNCH)
#define KV_STR  144
#define KV_TILE (64 * KV_STR)
#define KV_STG  (2 * KV_TILE)

__global__ __launch_bounds__(256, 2) void kv_mma_kernel(
    const __half* __restrict__ KH, const __half* __restrict__ VH,
    float* __restrict__ kv)
{
    __shared__ char smem[3 * KV_STG];
    const uint32_t sb = smem_u32(smem);

    const int bh = blockIdx.x;
    const int b = bh >> 4, h = bh & 15;
    const int chunk = blockIdx.y;
    const int tid = threadIdx.x;
    const int wid = tid >> 5;
    const int lane = tid & 31;
    const int warp_m = wid >> 1;
    const int warp_n = wid & 1;

    const size_t tokBase = (size_t)b * Nseq + (size_t)chunk * KVTOK;

    const int atr = (lane & 7) + ((lane >> 4) << 3);
    const int atc = ((lane >> 3) & 1) * 16;
    const int btr = (lane & 7) + ((lane >> 3) & 1) * 8;
    const int btc = (lane >> 4) * 16;

    float acc[4][4];
#pragma unroll
    for (int nt = 0; nt < 4; ++nt)
#pragma unroll
        for (int j = 0; j < 4; ++j) acc[nt][j] = 0.f;

    const int niter = KVTOK / 64;

    auto load_tile = [&](int s, int it) {
        const uint32_t stage = sb + (uint32_t)s * KV_STG;
#pragma unroll
        for (int i = 0; i < 4; ++i) {
            int idx = tid + i * 256;
            int tile = idx >> 9;
            int w = idx & 511;
            int row = w >> 3, cb = w & 7;
            const __half* gp = tile ? VH : KH;
            const void* ga = gp + (tokBase + (size_t)it * 64 + row) * EMBED + h * HDIM + cb * 8;
            uint32_t so = stage + (uint32_t)tile * KV_TILE + (uint32_t)row * KV_STR + cb * 16;
            CP_ASYNC16(so, ga);
        }
        CP_COMMIT();
    };

    load_tile(0, 0);
    load_tile(1, 1);

    for (int it = 0; it < niter; ++it) {
        if (it == niter - 1) { CP_WAIT(0); } else { CP_WAIT(1); }
        __syncthreads();

        if (it + 2 < niter)
            load_tile((it + 2) % 3, it + 2);

        const uint32_t st = sb + (uint32_t)(it % 3) * KV_STG;
        const uint32_t kb = st;
        const uint32_t vb = st + KV_TILE;

#pragma unroll
        for (int ts = 0; ts < 4; ++ts) {
            const int t0 = ts * 16;
            uint32_t a4[4];
            ldsm4t(a4, kb + (uint32_t)(t0 + atr) * KV_STR
                      + (uint32_t)(warp_m * 32) + atc);
            uint32_t br[4][2];
#pragma unroll
            for (int nt2 = 0; nt2 < 2; ++nt2) {
                uint32_t t4[4];
                ldsm4t(t4, vb + (uint32_t)(t0 + btr) * KV_STR
                          + (uint32_t)(warp_n * 64 + nt2 * 32) + btc);
                br[nt2*2][0]   = t4[0]; br[nt2*2][1]   = t4[1];
                br[nt2*2+1][0] = t4[2]; br[nt2*2+1][1] = t4[3];
            }
#pragma unroll
            for (int nt = 0; nt < 4; ++nt)
                mma16816(acc[nt], a4, br[nt]);
        }
    }

    float* kvp = kv + (size_t)bh * (HDIM * HDIM);
#pragma unroll
    for (int nt = 0; nt < 4; ++nt) {
#pragma unroll
        for (int hh = 0; hh < 2; ++hh) {
            const int d = warp_m * 16 + (lane >> 2) + hh * 8;
            const int e = warp_n * 32 + nt * 8 + (lane & 3) * 2;
            atomicAdd(kvp + d * HDIM + e,     acc[nt][hh * 2 + 0]);
            atomicAdd(kvp + d * HDIM + e + 1, acc[nt][hh * 2 + 1]);
        }
    }
}

// ---------------------------------------------------------------------------
// kvT convert
// ---------------------------------------------------------------------------
__global__ __launch_bounds__(256) void kvT_cvt_kernel(
    const float* __restrict__ kv, __half* __restrict__ kvTh)
{
    const int bh = blockIdx.x;
    const int tid = threadIdx.x;
    __shared__ float s[64][65];
    for (int i = tid; i < 4096; i += 256)
        s[i >> 6][i & 63] = kv[(size_t)bh * 4096 + i];
    __syncthreads();
    for (int i = tid; i < 4096; i += 256) {
        const int e = i >> 6, d = i & 63;
        kvTh[(size_t)bh * 4096 + i] = __float2half(s[d][e]);
    }
}

// ---------------------------------------------------------------------------
// attn numerator via MMA + fused denominator; 2 token tiles per CTA
// ---------------------------------------------------------------------------
#define AT_STR 144
__global__ __launch_bounds__(256) void attn_mma_kernel(
    const __half* __restrict__ Qh, const __half* __restrict__ kvTh,
    const float* __restrict__ ksum, __half* __restrict__ atH)
{
    __shared__ char smem[2 * 128 * AT_STR + 64 * AT_STR];
    __shared__ float ks_s[64];
    __shared__ float dinv_s[128];
    const uint32_t sq0 = smem_u32(smem);
    const uint32_t sq1 = sq0 + 128 * AT_STR;
    const uint32_t skt = sq0 + 2 * 128 * AT_STR;

    const int bh = blockIdx.x;
    const int b = bh >> 4, h = bh & 15;
    const int tt0 = blockIdx.y * 2;
    const int tid = threadIdx.x;
    const int wid = tid >> 5;
    const int lane = tid & 31;
    const int warp_m = wid >> 1;
    const int warp_n = wid & 1;

#pragma unroll
    for (int i = 0; i < 4; ++i) {
        int idx = tid + i * 256;
        int row = idx >> 3, cb = idx & 7;
        const void* ga = Qh + ((size_t)b * Nseq + tt0 * 128 + row) * EMBED + h * HDIM + cb * 8;
        CP_ASYNC16(sq0 + (uint32_t)row * AT_STR + cb * 16, ga);
    }
#pragma unroll
    for (int i = 0; i < 2; ++i) {
        int idx = tid + i * 256;
        int row = idx >> 3, cb = idx & 7;
        const void* ga = kvTh + (size_t)bh * 4096 + row * 64 + cb * 8;
        CP_ASYNC16(skt + (uint32_t)row * AT_STR + cb * 16, ga);
    }
    CP_COMMIT();
#pragma unroll
    for (int i = 0; i < 4; ++i) {
        int idx = tid + i * 256;
        int row = idx >> 3, cb = idx & 7;
        const void* ga = Qh + ((size_t)b * Nseq + (tt0 + 1) * 128 + row) * EMBED + h * HDIM + cb * 8;
        CP_ASYNC16(sq1 + (uint32_t)row * AT_STR + cb * 16, ga);
    }
    CP_COMMIT();

    if (tid < 64) ks_s[tid] = ksum[bh * 64 + tid];

    const int a_r = lane & 15;
    const int a_c = (lane >> 4) * 8;
    const int b_n = ((lane >> 4) << 3) + (lane & 7);
    const int b_k = ((lane >> 3) & 1) * 8;

#pragma unroll
    for (int t2 = 0; t2 < 2; ++t2) {
        const uint32_t sq = (t2 == 0) ? sq0 : sq1;
        if (t2 == 0) { CP_WAIT(1); } else { CP_WAIT(0); }
        __syncthreads();

        if (tid < 128) {
            const uint32_t qrow = sq + (uint32_t)tid * AT_STR;
            float d = 0.f;
#pragma unroll
            for (int j = 0; j < 32; ++j) {
                uint32_t packed;
                asm volatile("ld.shared.b32 %0, [%1];" : "=r"(packed) : "r"(qrow + j * 4));
                __half2 q2 = *reinterpret_cast<__half2*>(&packed);
                float2 qf = __half22float2(q2);
                d = fmaf(qf.x, ks_s[2 * j], d);
                d = fmaf(qf.y, ks_s[2 * j + 1], d);
            }
            dinv_s[tid] = 1.0f / (d + 1e-6f);
        }
        __syncthreads();

        float acc[2][4][4];
#pragma unroll
        for (int mt = 0; mt < 2; ++mt)
#pragma unroll
            for (int nt = 0; nt < 4; ++nt)
#pragma unroll
                for (int j = 0; j < 4; ++j) acc[mt][nt][j] = 0.f;

#pragma unroll
        for (int ks = 0; ks < 4; ++ks) {
            const int k0 = ks * 16;
            uint32_t ar[2][4];
#pragma unroll
            for (int mt = 0; mt < 2; ++mt) {
                uint32_t off = (uint32_t)(warp_m * 32 + mt * 16 + a_r) * AT_STR
                             + (uint32_t)(k0 + a_c) * 2;
                ldsm4(ar[mt], sq + off);
            }
            uint32_t br[4][2];
#pragma unroll
            for (int nt2 = 0; nt2 < 2; ++nt2) {
                uint32_t off = (uint32_t)(warp_n * 32 + nt2 * 16 + b_n) * AT_STR
                             + (uint32_t)(k0 + b_k) * 2;
                uint32_t t4[4];
                ldsm4(t4, skt + off);
                br[nt2*2][0] = t4[0]; br[nt2*2][1] = t4[1];
                br[nt2*2+1][0] = t4[2]; br[nt2*2+1][1] = t4[3];
            }
#pragma unroll
            for (int mt = 0; mt < 2; ++mt)
#pragma unroll
                for (int nt = 0; nt < 4; ++nt)
                    mma16816(acc[mt][nt], ar[mt], br[nt]);
        }

#pragma unroll
        for (int mt = 0; mt < 2; ++mt) {
#pragma unroll
            for (int hh = 0; hh < 2; ++hh) {
                const int rloc = warp_m * 32 + mt * 16 + (lane >> 2) + hh * 8;
                const float dv = dinv_s[rloc];
                const size_t ob = ((size_t)b * Nseq + (tt0 + t2) * 128 + rloc) * EMBED + h * HDIM;
#pragma unroll
                for (int nt = 0; nt < 4; ++nt) {
                    const int col = warp_n * 32 + nt * 8 + (lane & 3) * 2;
                    float f0 = acc[mt][nt][hh * 2 + 0] * dv;
                    float f1 = acc[mt][nt][hh * 2 + 1] * dv;
                    *reinterpret_cast<__half2*>(atH + ob + col) = __floats2half2_rn(f0, f1);
                }
            }
        }
        if (t2 == 0) __syncthreads();
    }
}

// ---------------------------------------------------------------------------
// launch
// ---------------------------------------------------------------------------
extern "C" void kernel_launch(void* const* d_in, const int* in_sizes, int n_in,
                              void* d_out, int out_size)
{
    const float* query   = (const float*)d_in[0];
    const float* key_    = (const float*)d_in[1];
    const float* value   = (const float*)d_in[2];
    const float* Wq_down = (const float*)d_in[3];
    const float* Wq_up   = (const float*)d_in[4];
    const float* bq_up   = (const float*)d_in[5];
    const float* Wk_down = (const float*)d_in[6];
    const float* Wk_up   = (const float*)d_in[7];
    const float* bk_up   = (const float*)d_in[8];
    const float* Wv_down = (const float*)d_in[9];
    const float* Wv_up   = (const float*)d_in[10];
    const float* bv_up   = (const float*)d_in[11];
    const float* Wo      = (const float*)d_in[12];
    const float* bo      = (const float*)d_in[13];
    float* out = (float*)d_out;

    __half *QH, *KH, *VH, *atH, *kvTh;
    float *KVKS;
    cudaGetSymbolAddress((void**)&QH,   g_QH);
    cudaGetSymbolAddress((void**)&KH,   g_KH);
    cudaGetSymbolAddress((void**)&VH,   g_VH);
    cudaGetSymbolAddress((void**)&atH,  g_atH);
    cudaGetSymbolAddress((void**)&kvTh, g_kvTh);
    cudaGetSymbolAddress((void**)&KVKS, g_kvks);
    float* KV = KVKS;
    float* KS = KVKS + KV_ELEMS;

    cudaFuncSetAttribute((const void*)gemm_fused<0>, cudaFuncAttributeMaxDynamicSharedMemorySize, SMEM_GEMM);
    cudaFuncSetAttribute((const void*)gemm_fused<1>, cudaFuncAttributeMaxDynamicSharedMemorySize, SMEM_GEMM);
    cudaFuncSetAttribute((const void*)gemm_fused<2>, cudaFuncAttributeMaxDynamicSharedMemorySize, SMEM_GEMM);

    static cudaStream_t s2 = nullptr;
    static cudaEvent_t evFork = nullptr, evJoin = nullptr;
    static cudaEvent_t evFork2 = nullptr, evJoin2 = nullptr;
    if (s2 == nullptr) {
        cudaStreamCreateWithFlags(&s2, cudaStreamNonBlocking);
        cudaEventCreateWithFlags(&evFork,  cudaEventDisableTiming);
        cudaEventCreateWithFlags(&evJoin,  cudaEventDisableTiming);
        cudaEventCreateWithFlags(&evFork2, cudaEventDisableTiming);
        cudaEventCreateWithFlags(&evJoin2, cudaEventDisableTiming);
    }

    const dim3 blk(256);
    const int nCvtBlk = MTOK * EMBED / 8 / 256;   // 16384

    // weights first on main (needed by down(q))
    wcvt_kernel<<<(6 * WSEG4 + EMBED*EMBED/4 + 255) / 256, blk>>>(
        Wq_down, Wq_up, Wk_down, Wk_up, Wv_down, Wv_up, Wo);

    // fork 1: k/v converts + accumulator zero on side stream,
    //         q convert + down(q) on main — runs concurrently
    cudaEventRecord(evFork, 0);
    cudaStreamWaitEvent(s2, evFork, 0);
    {
        const int nz = KV_ELEMS + KS_ELEMS;
        zero_kernel<<<(nz + 255) / 256, blk, 0, s2>>>(KVKS, nz);
    }
    cvt1_kernel<<<nCvtBlk, blk, 0, s2>>>(key_,   1);
    cvt1_kernel<<<nCvtBlk, blk, 0, s2>>>(value,  2);
    cudaEventRecord(evJoin, s2);

    cvt1_kernel<<<nCvtBlk, blk>>>(query, 0);
    gemm_fused<0><<<dim3(RANK / 128, MTOK / 128, 1), blk, SMEM_GEMM>>>(
        nullptr, nullptr, nullptr, nullptr, 0);          // down(q)

    // join 1
    cudaStreamWaitEvent(0, evJoin, 0);

    gemm_fused<0><<<dim3(RANK / 128, MTOK / 128, 2), blk, SMEM_GEMM>>>(
        nullptr, nullptr, nullptr, nullptr, 1);          // down(k,v)

    // up(k,v) first (z = 1,2; elu for k; ksum fused for z==1)
    gemm_fused<1><<<dim3(EMBED / 128, MTOK / 128, 2), blk, SMEM_GEMM>>>(
        bq_up, bk_up, bv_up, nullptr, 1);

    // fork 2: kv chain on side stream, up(q) on main — runs concurrently
    cudaEventRecord(evFork2, 0);
    cudaStreamWaitEvent(s2, evFork2, 0);
    kv_mma_kernel<<<dim3(BH, KVNCH), blk, 0, s2>>>(KH, VH, KV);
    kvT_cvt_kernel<<<BH, blk, 0, s2>>>(KV, kvTh);
    cudaEventRecord(evJoin2, s2);

    gemm_fused<1><<<dim3(EMBED / 128, MTOK / 128, 1), blk, SMEM_GEMM>>>(
        bq_up, bk_up, bv_up, nullptr, 0);                // up(q)

    // join 2: attn needs kvTh (+ KS from up(k))
    cudaStreamWaitEvent(0, evJoin2, 0);

    // attention numerator (MMA) + fused denom + divide (2 tiles/CTA)
    attn_mma_kernel<<<dim3(BH, Nseq / 256), blk>>>(QH, kvTh, KS, atH);

    // output projection (fp32 out)
    gemm_fused<2><<<dim3(EMBED / 128, MTOK / 128, 1), blk, SMEM_GEMM>>>(
        bo, nullptr, nullptr, out, 0);
}